// round 4
// baseline (speedup 1.0000x reference)
#include <cuda_runtime.h>
#include <cuda_bf16.h>
#include <math.h>
#include <stdint.h>

// Problem constants
#define BATCH     1024
#define FDIM      1024
#define NCONCEPT  32768
#define INV_T     10.0f   // 1 / 0.1

#define TILE_B    16384          // one 128x128-int8 swizzled tile (128 rows * 128 B)
#define KCHUNKS   8              // 1024 / 128
#define STAGE_B   (4 * TILE_B)   // A1, A0, B1, B0 per stage = 64 KB
#define NSTAGES   3
#define SMEM_TOTAL (1024 + NSTAGES * STAGE_B)

// ---------------- scratch (device globals; no allocation allowed) ----------
__device__ float g_P[BATCH * FDIM];                      // projection output
__device__ float g_S[(size_t)BATCH * NCONCEPT];          // similarities (134 MB)
__device__ __align__(256) char g_A1[(size_t)BATCH * FDIM];        // 1 MB
__device__ __align__(256) char g_A0[(size_t)BATCH * FDIM];
__device__ __align__(256) char g_B1[(size_t)NCONCEPT * FDIM];     // 32 MB
__device__ __align__(256) char g_B0[(size_t)NCONCEPT * FDIM];
__device__ float g_sA[BATCH];
__device__ float g_sB[NCONCEPT];

// ---------------------------------------------------------------------------
// PTX helpers (baseline ISA only)
// ---------------------------------------------------------------------------
__device__ __forceinline__ uint32_t sm_u32(const void* p) {
    uint32_t a;
    asm("{ .reg .u64 t; cvta.to.shared.u64 t, %1; cvt.u32.u64 %0, t; }"
        : "=r"(a) : "l"(p));
    return a;
}

__device__ __forceinline__ void mbar_wait(uint32_t addr, int phase) {
    asm volatile(
        "{\n\t.reg .pred P;\n\t"
        "WL_%=:\n\t"
        "mbarrier.try_wait.parity.acquire.cta.shared::cta.b64 P, [%0], %1, 0x989680;\n\t"
        "@P bra.uni WD_%=;\n\t"
        "bra.uni WL_%=;\n\t"
        "WD_%=:\n\t}"
        :: "r"(addr), "r"((uint32_t)phase) : "memory");
}

#define LDSM4(R, addr) \
    asm volatile("ldmatrix.sync.aligned.m8n8.x4.shared.b16 {%0,%1,%2,%3}, [%4];" \
        : "=r"((R)[0]), "=r"((R)[1]), "=r"((R)[2]), "=r"((R)[3]) : "r"(addr))

#define MMA_S8(C, A, b0_, b1_) \
    asm volatile("mma.sync.aligned.m16n8k32.row.col.s32.s8.s8.s32 " \
        "{%0,%1,%2,%3}, {%4,%5,%6,%7}, {%8,%9}, {%0,%1,%2,%3};" \
        : "+r"((C)[0]), "+r"((C)[1]), "+r"((C)[2]), "+r"((C)[3]) \
        : "r"((A)[0]), "r"((A)[1]), "r"((A)[2]), "r"((A)[3]), "r"(b0_), "r"(b1_))

#define BULK_LOAD(dst, src, bar) \
    asm volatile("cp.async.bulk.shared::cluster.global.mbarrier::complete_tx::bytes " \
        "[%0], [%1], %2, [%3];" \
        :: "r"(dst), "l"(src), "r"((uint32_t)TILE_B), "r"(bar) : "memory")

// ---------------------------------------------------------------------------
// fp32 SGEMM (projection only): C[m,n] = sum_k A[m,k]*B[n,k] + bias[n]
// ---------------------------------------------------------------------------
template <bool BIAS>
__global__ void __launch_bounds__(256, 2)
sgemm128_nt(const float* __restrict__ A, const float* __restrict__ B,
            const float* __restrict__ bias, float* __restrict__ C,
            int M, int N, int K)
{
    __shared__ __align__(16) float As[16][132];
    __shared__ __align__(16) float Bs[16][132];

    const int tid = threadIdx.x;
    const int bm  = blockIdx.y * 128;
    const int bn  = blockIdx.x * 128;
    const int lr = tid >> 2;
    const int lk = (tid & 3) << 2;

    const float* Ag = A + (size_t)(bm + lr) * K + lk;
    const float* Bg = B + (size_t)(bn + lr) * K + lk;
    const size_t Aoff64 = (size_t)64 * K;

    const int r = tid >> 4;
    const int c = tid & 15;

    float acc[8][8];
#pragma unroll
    for (int i = 0; i < 8; ++i)
#pragma unroll
        for (int j = 0; j < 8; ++j) acc[i][j] = 0.f;

    for (int kt = 0; kt < K; kt += 16) {
        const float4 a0 = *(const float4*)(Ag + kt);
        const float4 a1 = *(const float4*)(Ag + Aoff64 + kt);
        const float4 b0 = *(const float4*)(Bg + kt);
        const float4 b1 = *(const float4*)(Bg + Aoff64 + kt);

        __syncthreads();
        As[lk + 0][lr] = a0.x; As[lk + 1][lr] = a0.y;
        As[lk + 2][lr] = a0.z; As[lk + 3][lr] = a0.w;
        As[lk + 0][lr + 64] = a1.x; As[lk + 1][lr + 64] = a1.y;
        As[lk + 2][lr + 64] = a1.z; As[lk + 3][lr + 64] = a1.w;
        Bs[lk + 0][lr] = b0.x; Bs[lk + 1][lr] = b0.y;
        Bs[lk + 2][lr] = b0.z; Bs[lk + 3][lr] = b0.w;
        Bs[lk + 0][lr + 64] = b1.x; Bs[lk + 1][lr + 64] = b1.y;
        Bs[lk + 2][lr + 64] = b1.z; Bs[lk + 3][lr + 64] = b1.w;
        __syncthreads();

#pragma unroll
        for (int kk = 0; kk < 16; ++kk) {
            const float4 fa0 = *(const float4*)&As[kk][r * 4];
            const float4 fa1 = *(const float4*)&As[kk][64 + r * 4];
            const float4 fb0 = *(const float4*)&Bs[kk][c * 4];
            const float4 fb1 = *(const float4*)&Bs[kk][64 + c * 4];
            const float ra[8] = {fa0.x, fa0.y, fa0.z, fa0.w, fa1.x, fa1.y, fa1.z, fa1.w};
            const float rb[8] = {fb0.x, fb0.y, fb0.z, fb0.w, fb1.x, fb1.y, fb1.z, fb1.w};
#pragma unroll
            for (int i = 0; i < 8; ++i)
#pragma unroll
                for (int j = 0; j < 8; ++j)
                    acc[i][j] += ra[i] * rb[j];
        }
    }

    float bias0[4], bias1[4];
    if (BIAS) {
#pragma unroll
        for (int j = 0; j < 4; ++j) {
            bias0[j] = bias[bn + c * 4 + j];
            bias1[j] = bias[bn + 64 + c * 4 + j];
        }
    }
#pragma unroll
    for (int i = 0; i < 8; ++i) {
        const int row = bm + ((i < 4) ? (r * 4 + i) : (64 + r * 4 + (i - 4)));
        float4 v0, v1;
        v0.x = acc[i][0]; v0.y = acc[i][1]; v0.z = acc[i][2]; v0.w = acc[i][3];
        v1.x = acc[i][4]; v1.y = acc[i][5]; v1.z = acc[i][6]; v1.w = acc[i][7];
        if (BIAS) {
            v0.x += bias0[0]; v0.y += bias0[1]; v0.z += bias0[2]; v0.w += bias0[3];
            v1.x += bias1[0]; v1.y += bias1[1]; v1.z += bias1[2]; v1.w += bias1[3];
        }
        float* crow = C + (size_t)row * N + bn;
        *(float4*)(crow + c * 4)      = v0;
        *(float4*)(crow + 64 + c * 4) = v1;
    }
}

// ---------------------------------------------------------------------------
// Row quantization to two int8 limbs with per-row scale, writing pre-swizzled
// 128x128 tiles. One CTA per row (256 threads, 4 elems/thread).
//   q  = x * 127 / max|row|,  l1 = rint(q), l0 = rint((q-l1)*256) clamped.
// If NORM, scale folds in 1/||row|| so the GEMM output is the normalized dot:
//   s_row = max|row| / (127 * ||row||)      (else  max|row| / 127)
// Tile layout: tile = (row>>7)*KCHUNKS + (k>>7); swizzled (row&127)*128+(k&127).
// ---------------------------------------------------------------------------
template <bool NORM>
__global__ void __launch_bounds__(256)
quant_rows(const float4* __restrict__ src, char* __restrict__ q1,
           char* __restrict__ q0, float* __restrict__ scale)
{
    const int row = blockIdx.x;
    const int tid = threadIdx.x;
    const float4 v = src[(size_t)row * 256 + tid];
    const float x[4] = {v.x, v.y, v.z, v.w};

    float am = fmaxf(fmaxf(fabsf(x[0]), fabsf(x[1])), fmaxf(fabsf(x[2]), fabsf(x[3])));
    float ss = 0.f;
    if (NORM) ss = x[0]*x[0] + x[1]*x[1] + x[2]*x[2] + x[3]*x[3];

    __shared__ float rmax[256];
    __shared__ float rsum[256];
    rmax[tid] = am;
    if (NORM) rsum[tid] = ss;
    __syncthreads();
#pragma unroll
    for (int off = 128; off > 0; off >>= 1) {
        if (tid < off) {
            rmax[tid] = fmaxf(rmax[tid], rmax[tid + off]);
            if (NORM) rsum[tid] += rsum[tid + off];
        }
        __syncthreads();
    }
    const float mx  = fmaxf(rmax[0], 1e-30f);
    const float inv = 127.0f / mx;

    uint32_t p1 = 0, p0 = 0;
#pragma unroll
    for (int j = 0; j < 4; ++j) {
        const float q = x[j] * inv;
        const int i1  = __float2int_rn(q);
        int i0        = __float2int_rn((q - (float)i1) * 256.0f);
        i0 = max(-127, min(127, i0));
        p1 |= ((uint32_t)(uint8_t)(int8_t)i1) << (j * 8);
        p0 |= ((uint32_t)(uint8_t)(int8_t)i0) << (j * 8);
    }

    const int k = tid * 4;
    const int tile = (row >> 7) * KCHUNKS + (k >> 7);
    uint32_t off = (uint32_t)((row & 127) * 128 + (k & 127));
    off ^= (uint32_t)(row & 7) << 4;          // SW128
    *(uint32_t*)(q1 + (size_t)tile * TILE_B + off) = p1;
    *(uint32_t*)(q0 + (size_t)tile * TILE_B + off) = p0;

    if (tid == 0) {
        float s = mx * (1.0f / 127.0f);
        if (NORM) s /= fmaxf(sqrtf(rsum[0]), 1e-12f);
        scale[row] = s;
    }
}

// ---------------------------------------------------------------------------
// Similarity GEMM via int8 mma.sync m16n8k32, two-limb split (~fp32 accuracy):
//   sim[m,n] = sA[m]*sB[n] * (sum a1*b1 + (sum a1*b0 + a0*b1)/256)
// CTA tile 128x128 (8 warps, 4M x 2N, warp tile 32x64). K chunks of 128 int8.
// cp.async.bulk (4 x 16KB per stage) + mbarrier expect_tx, 3-stage pipeline.
// ---------------------------------------------------------------------------
__global__ void __launch_bounds__(256, 1)
sim_mma(const char* __restrict__ A1, const char* __restrict__ A0,
        const char* __restrict__ B1, const char* __restrict__ B0,
        const float* __restrict__ sA, const float* __restrict__ sB,
        float* __restrict__ S)
{
    extern __shared__ char smem_raw[];
    const uint32_t sbase = sm_u32(smem_raw);
    const uint32_t mbar0 = sbase;                          // 3 x 8B mbarriers
    const uint32_t data0 = (sbase + 24u + 1023u) & ~1023u; // 1024-aligned stages

    const int tid = threadIdx.x;
    const int w = tid >> 5, l = tid & 31;
    const int wm = w & 3;         // M block of 32
    const int wn = w >> 2;        // N block of 64
    const int mb = blockIdx.x;    // 0..7
    const int nb = blockIdx.y;    // 0..255

    if (tid == 0) {
#pragma unroll
        for (int s = 0; s < NSTAGES; ++s)
            asm volatile("mbarrier.init.shared.b64 [%0], 1;" :: "r"(mbar0 + s * 8) : "memory");
    }
    __syncthreads();

    // per-thread ldmatrix addressing (identical structure to bf16 case; rows
    // are 128B, offsets reinterpreted as int8 k-bytes)
    const int rowA  = wm * 32 + (l & 15);
    const uint32_t hA = (uint32_t)(l >> 4) << 4;             // 0 / 16 B
    const int rowB0 = wn * 64 + (l & 7) + ((l & 16) >> 1);
    const uint32_t hB = (uint32_t)(l & 8) << 1;              // 0 / 16 B
    const uint32_t swz = (uint32_t)(l & 7) << 4;

    int acc1[2][8][4];    // weight 256 (a1*b1)
    int accX[2][8][4];    // weight 1   (a1*b0 + a0*b1)
#pragma unroll
    for (int i = 0; i < 2; ++i)
#pragma unroll
        for (int j = 0; j < 8; ++j)
#pragma unroll
            for (int q = 0; q < 4; ++q) { acc1[i][j][q] = 0; accX[i][j][q] = 0; }

    auto issue = [&](int kc, int s) {
        const uint32_t d = data0 + s * STAGE_B;
        const uint32_t bar = mbar0 + s * 8;
        const size_t aoff = ((size_t)mb * KCHUNKS + kc) * TILE_B;
        const size_t boff = ((size_t)nb * KCHUNKS + kc) * TILE_B;
        asm volatile("mbarrier.arrive.expect_tx.shared.b64 _, [%0], %1;"
                     :: "r"(bar), "r"((uint32_t)STAGE_B) : "memory");
        BULK_LOAD(d,              A1 + aoff, bar);
        BULK_LOAD(d + 1 * TILE_B, A0 + aoff, bar);
        BULK_LOAD(d + 2 * TILE_B, B1 + boff, bar);
        BULK_LOAD(d + 3 * TILE_B, B0 + boff, bar);
    };

    if (tid == 0) { issue(0, 0); issue(1, 1); }

    int ph[NSTAGES] = {0, 0, 0};

    for (int kc = 0; kc < KCHUNKS; ++kc) {
        const int s = kc % NSTAGES;
        mbar_wait(mbar0 + s * 8, ph[s]);
        ph[s] ^= 1;
        __syncthreads();   // all warps done with the stage being reissued
        if (tid == 0 && kc + 2 < KCHUNKS) issue(kc + 2, (kc + 2) % NSTAGES);

        const uint32_t a1b = data0 + s * STAGE_B;
        const uint32_t a0b = a1b + 1 * TILE_B;
        const uint32_t b1b = a1b + 2 * TILE_B;
        const uint32_t b0b = a1b + 3 * TILE_B;

#pragma unroll
        for (int ks = 0; ks < 4; ++ks) {          // 4 x k32 per 128-chunk
            uint32_t a1f[2][4], a0f[2][4];
#pragma unroll
            for (int mi = 0; mi < 2; ++mi) {
                const uint32_t pa =
                    ((uint32_t)((rowA + mi * 16) * 128) + (uint32_t)(ks * 32) + hA) ^ swz;
                LDSM4(a1f[mi], a1b + pa);
                LDSM4(a0f[mi], a0b + pa);
            }
#pragma unroll
            for (int nk = 0; nk < 4; ++nk) {
                const uint32_t pb =
                    ((uint32_t)((rowB0 + nk * 16) * 128) + (uint32_t)(ks * 32) + hB) ^ swz;
                uint32_t b1f[4], b0f[4];
                LDSM4(b1f, b1b + pb);
                LDSM4(b0f, b0b + pb);
#pragma unroll
                for (int mi = 0; mi < 2; ++mi) {
                    MMA_S8(acc1[mi][nk * 2 + 0], a1f[mi], b1f[0], b1f[1]);
                    MMA_S8(accX[mi][nk * 2 + 0], a1f[mi], b0f[0], b0f[1]);
                    MMA_S8(accX[mi][nk * 2 + 0], a0f[mi], b1f[0], b1f[1]);
                    MMA_S8(acc1[mi][nk * 2 + 1], a1f[mi], b1f[2], b1f[3]);
                    MMA_S8(accX[mi][nk * 2 + 1], a1f[mi], b0f[2], b0f[3]);
                    MMA_S8(accX[mi][nk * 2 + 1], a0f[mi], b1f[2], b1f[3]);
                }
            }
        }
    }

    // epilogue: combine limbs, apply scales, write S
    const int gm0 = mb * 128 + wm * 32 + (l >> 2);
    const int gn0 = nb * 128 + wn * 64 + (l & 3) * 2;
#pragma unroll
    for (int mi = 0; mi < 2; ++mi) {
        const float sa0 = sA[gm0 + mi * 16];
        const float sa1 = sA[gm0 + mi * 16 + 8];
#pragma unroll
        for (int nk = 0; nk < 4; ++nk) {
#pragma unroll
            for (int hf = 0; hf < 2; ++hf) {
                const int n = gn0 + nk * 16 + hf * 8;
                const float sb0 = sB[n];
                const float sb1 = sB[n + 1];
                const int* c1 = acc1[mi][nk * 2 + hf];
                const int* cx = accX[mi][nk * 2 + hf];
                float* p = S + (size_t)(gm0 + mi * 16) * NCONCEPT + n;
                float2 v0, v1;
                v0.x = ((float)c1[0] + (float)cx[0] * (1.0f/256.0f)) * (sa0 * sb0);
                v0.y = ((float)c1[1] + (float)cx[1] * (1.0f/256.0f)) * (sa0 * sb1);
                v1.x = ((float)c1[2] + (float)cx[2] * (1.0f/256.0f)) * (sa1 * sb0);
                v1.y = ((float)c1[3] + (float)cx[3] * (1.0f/256.0f)) * (sa1 * sb1);
                *(float2*)p = v0;
                *(float2*)(p + (size_t)8 * NCONCEPT) = v1;
            }
        }
    }
}

// ---------------------------------------------------------------------------
// Per-row softmax(sim * INV_T) + argmax. One CTA (256 threads) per row.
// ---------------------------------------------------------------------------
__global__ void __launch_bounds__(256)
softmax_row(const float* __restrict__ S,
            float* __restrict__ act,
            float* __restrict__ bidx)
{
    const int row = blockIdx.x;
    const int tid = threadIdx.x;
    const float* s = S + (size_t)row * NCONCEPT;

    float m = -INFINITY;
    float Z = 0.f;
    int   bi = 0;

    for (int j = tid; j < NCONCEPT; j += 256) {
        const float v = s[j];
        if (v > m) {
            Z = Z * __expf((m - v) * INV_T) + 1.0f;
            m = v;
            bi = j;
        } else {
            Z += __expf((v - m) * INV_T);
        }
    }

    __shared__ float sm[256];
    __shared__ float sz[256];
    __shared__ int   si[256];
    sm[tid] = m; sz[tid] = Z; si[tid] = bi;
    __syncthreads();

#pragma unroll
    for (int off = 128; off > 0; off >>= 1) {
        if (tid < off) {
            const float m1 = sm[tid],       z1 = sz[tid];
            const float m2 = sm[tid + off], z2 = sz[tid + off];
            const int   i1 = si[tid],       i2 = si[tid + off];
            if (m2 > m1 || (m2 == m1 && i2 < i1)) {
                sm[tid] = m2;
                sz[tid] = z2 + z1 * __expf((m1 - m2) * INV_T);
                si[tid] = i2;
            } else {
                sz[tid] = z1 + z2 * __expf((m2 - m1) * INV_T);
            }
        }
        __syncthreads();
    }

    const float M    = sm[0];
    const float invZ = 1.0f / sz[0];
    float* a = act + (size_t)row * NCONCEPT;
    for (int j = tid; j < NCONCEPT; j += 256)
        a[j] = __expf((s[j] - M) * INV_T) * invZ;

    if (tid == 0) bidx[row] = (float)si[0];
}

// ---------------------------------------------------------------------------
extern "C" void kernel_launch(void* const* d_in, const int* in_sizes, int n_in,
                              void* d_out, int out_size)
{
    const float* features   = (const float*)d_in[0];  // [1024, 1024]
    const float* W          = (const float*)d_in[1];  // [1024, 1024]
    const float* b          = (const float*)d_in[2];  // [1024]
    const float* prototypes = (const float*)d_in[3];  // [32768, 1024]

    float* out  = (float*)d_out;
    float* act  = out;                                   // [1024, 32768]
    float* bidx = out + (size_t)BATCH * NCONCEPT;        // [1024] as float

    float *pP = nullptr, *pS = nullptr, *psA = nullptr, *psB = nullptr;
    char *pA1 = nullptr, *pA0 = nullptr, *pB1 = nullptr, *pB0 = nullptr;
    cudaGetSymbolAddress((void**)&pP,  g_P);
    cudaGetSymbolAddress((void**)&pS,  g_S);
    cudaGetSymbolAddress((void**)&pA1, g_A1);
    cudaGetSymbolAddress((void**)&pA0, g_A0);
    cudaGetSymbolAddress((void**)&pB1, g_B1);
    cudaGetSymbolAddress((void**)&pB0, g_B0);
    cudaGetSymbolAddress((void**)&psA, g_sA);
    cudaGetSymbolAddress((void**)&psB, g_sB);

    cudaFuncSetAttribute(sim_mma, cudaFuncAttributeMaxDynamicSharedMemorySize, SMEM_TOTAL);

    // 1) projection: P = features @ W^T + b   [1024, 1024] (fp32)
    sgemm128_nt<true><<<dim3(FDIM / 128, BATCH / 128), 256>>>(
        features, W, b, pP, BATCH, FDIM, FDIM);

    // 2) quantize A rows (fold L2 norm into scale) and B rows to int8 limbs
    quant_rows<true><<<BATCH, 256>>>((const float4*)pP, pA1, pA0, psA);
    quant_rows<false><<<NCONCEPT, 256>>>((const float4*)prototypes, pB1, pB0, psB);

    // 3) similarities via int8 two-limb mma.sync (k32)
    sim_mma<<<dim3(BATCH / 128, NCONCEPT / 128), 256, SMEM_TOTAL>>>(
        pA1, pA0, pB1, pB0, psA, psB, pS);

    // 4) per-row softmax(S/T) + argmax
    softmax_row<<<BATCH, 256>>>(pS, act, bidx);
}

// round 5
// speedup vs baseline: 3.1398x; 3.1398x over previous
#include <cuda_runtime.h>
#include <cuda_fp16.h>
#include <math.h>
#include <stdint.h>

// Problem constants
#define BATCH     1024
#define FDIM      1024
#define NCONCEPT  32768
#define INV_T     10.0f   // 1 / 0.1

#define TILE_B    16384          // one 128x64-fp16 swizzled tile (128 rows * 128 B)
#define KCHUNKS   16             // 1024 / 64
#define STAGE_B   (3 * TILE_B)   // Ahi, Alo, Bhi per stage = 48 KB
#define NSTAGES   4
#define SMEM_TOTAL (1024 + NSTAGES * STAGE_B)
#define LO_SCALE  2048.0f        // 2^11: keeps A-lo limb in fp16 normal range

// ---------------- scratch (device globals; no allocation allowed) ----------
__device__ float g_P[BATCH * FDIM];                      // projection output
__device__ float g_S[(size_t)BATCH * NCONCEPT];          // similarities (134 MB)
__device__ __align__(256) char g_Ah[(size_t)BATCH * FDIM * 2];     // 2 MB
__device__ __align__(256) char g_Al[(size_t)BATCH * FDIM * 2];
__device__ __align__(256) char g_Bh[(size_t)NCONCEPT * FDIM * 2];  // 64 MB

// ---------------------------------------------------------------------------
// PTX helpers (baseline ISA only)
// ---------------------------------------------------------------------------
__device__ __forceinline__ uint32_t sm_u32(const void* p) {
    uint32_t a;
    asm("{ .reg .u64 t; cvta.to.shared.u64 t, %1; cvt.u32.u64 %0, t; }"
        : "=r"(a) : "l"(p));
    return a;
}

__device__ __forceinline__ void mbar_wait(uint32_t addr, int phase) {
    asm volatile(
        "{\n\t.reg .pred P;\n\t"
        "WL_%=:\n\t"
        "mbarrier.try_wait.parity.acquire.cta.shared::cta.b64 P, [%0], %1, 0x989680;\n\t"
        "@P bra.uni WD_%=;\n\t"
        "bra.uni WL_%=;\n\t"
        "WD_%=:\n\t}"
        :: "r"(addr), "r"((uint32_t)phase) : "memory");
}

#define LDSM4(R, addr) \
    asm volatile("ldmatrix.sync.aligned.m8n8.x4.shared.b16 {%0,%1,%2,%3}, [%4];" \
        : "=r"((R)[0]), "=r"((R)[1]), "=r"((R)[2]), "=r"((R)[3]) : "r"(addr))

// fp16 inputs, fp32 accumulate (main term)
#define MMA_F16_F32(C, A, b0_, b1_) \
    asm volatile("mma.sync.aligned.m16n8k16.row.col.f32.f16.f16.f32 " \
        "{%0,%1,%2,%3}, {%4,%5,%6,%7}, {%8,%9}, {%0,%1,%2,%3};" \
        : "+f"((C)[0]), "+f"((C)[1]), "+f"((C)[2]), "+f"((C)[3]) \
        : "r"((A)[0]), "r"((A)[1]), "r"((A)[2]), "r"((A)[3]), "r"(b0_), "r"(b1_))

// fp16 inputs, fp16 accumulate (correction term; 2 packed f16x2 regs)
#define MMA_F16_F16(C, A, b0_, b1_) \
    asm volatile("mma.sync.aligned.m16n8k16.row.col.f16.f16.f16.f16 " \
        "{%0,%1}, {%2,%3,%4,%5}, {%6,%7}, {%0,%1};" \
        : "+r"((C)[0]), "+r"((C)[1]) \
        : "r"((A)[0]), "r"((A)[1]), "r"((A)[2]), "r"((A)[3]), "r"(b0_), "r"(b1_))

#define BULK_LOAD(dst, src, bar) \
    asm volatile("cp.async.bulk.shared::cluster.global.mbarrier::complete_tx::bytes " \
        "[%0], [%1], %2, [%3];" \
        :: "r"(dst), "l"(src), "r"((uint32_t)TILE_B), "r"(bar) : "memory")

// ---------------------------------------------------------------------------
// fp32 SGEMM (projection only): C[m,n] = sum_k A[m,k]*B[n,k] + bias[n]
// ---------------------------------------------------------------------------
template <bool BIAS>
__global__ void __launch_bounds__(256, 2)
sgemm128_nt(const float* __restrict__ A, const float* __restrict__ B,
            const float* __restrict__ bias, float* __restrict__ C,
            int M, int N, int K)
{
    __shared__ __align__(16) float As[16][132];
    __shared__ __align__(16) float Bs[16][132];

    const int tid = threadIdx.x;
    const int bm  = blockIdx.y * 128;
    const int bn  = blockIdx.x * 128;
    const int lr = tid >> 2;
    const int lk = (tid & 3) << 2;

    const float* Ag = A + (size_t)(bm + lr) * K + lk;
    const float* Bg = B + (size_t)(bn + lr) * K + lk;
    const size_t Aoff64 = (size_t)64 * K;

    const int r = tid >> 4;
    const int c = tid & 15;

    float acc[8][8];
#pragma unroll
    for (int i = 0; i < 8; ++i)
#pragma unroll
        for (int j = 0; j < 8; ++j) acc[i][j] = 0.f;

    for (int kt = 0; kt < K; kt += 16) {
        const float4 a0 = *(const float4*)(Ag + kt);
        const float4 a1 = *(const float4*)(Ag + Aoff64 + kt);
        const float4 b0 = *(const float4*)(Bg + kt);
        const float4 b1 = *(const float4*)(Bg + Aoff64 + kt);

        __syncthreads();
        As[lk + 0][lr] = a0.x; As[lk + 1][lr] = a0.y;
        As[lk + 2][lr] = a0.z; As[lk + 3][lr] = a0.w;
        As[lk + 0][lr + 64] = a1.x; As[lk + 1][lr + 64] = a1.y;
        As[lk + 2][lr + 64] = a1.z; As[lk + 3][lr + 64] = a1.w;
        Bs[lk + 0][lr] = b0.x; Bs[lk + 1][lr] = b0.y;
        Bs[lk + 2][lr] = b0.z; Bs[lk + 3][lr] = b0.w;
        Bs[lk + 0][lr + 64] = b1.x; Bs[lk + 1][lr + 64] = b1.y;
        Bs[lk + 2][lr + 64] = b1.z; Bs[lk + 3][lr + 64] = b1.w;
        __syncthreads();

#pragma unroll
        for (int kk = 0; kk < 16; ++kk) {
            const float4 fa0 = *(const float4*)&As[kk][r * 4];
            const float4 fa1 = *(const float4*)&As[kk][64 + r * 4];
            const float4 fb0 = *(const float4*)&Bs[kk][c * 4];
            const float4 fb1 = *(const float4*)&Bs[kk][64 + c * 4];
            const float ra[8] = {fa0.x, fa0.y, fa0.z, fa0.w, fa1.x, fa1.y, fa1.z, fa1.w};
            const float rb[8] = {fb0.x, fb0.y, fb0.z, fb0.w, fb1.x, fb1.y, fb1.z, fb1.w};
#pragma unroll
            for (int i = 0; i < 8; ++i)
#pragma unroll
                for (int j = 0; j < 8; ++j)
                    acc[i][j] += ra[i] * rb[j];
        }
    }

    float bias0[4], bias1[4];
    if (BIAS) {
#pragma unroll
        for (int j = 0; j < 4; ++j) {
            bias0[j] = bias[bn + c * 4 + j];
            bias1[j] = bias[bn + 64 + c * 4 + j];
        }
    }
#pragma unroll
    for (int i = 0; i < 8; ++i) {
        const int row = bm + ((i < 4) ? (r * 4 + i) : (64 + r * 4 + (i - 4)));
        float4 v0, v1;
        v0.x = acc[i][0]; v0.y = acc[i][1]; v0.z = acc[i][2]; v0.w = acc[i][3];
        v1.x = acc[i][4]; v1.y = acc[i][5]; v1.z = acc[i][6]; v1.w = acc[i][7];
        if (BIAS) {
            v0.x += bias0[0]; v0.y += bias0[1]; v0.z += bias0[2]; v0.w += bias0[3];
            v1.x += bias1[0]; v1.y += bias1[1]; v1.z += bias1[2]; v1.w += bias1[3];
        }
        float* crow = C + (size_t)row * N + bn;
        *(float4*)(crow + c * 4)      = v0;
        *(float4*)(crow + 64 + c * 4) = v1;
    }
}

// ---------------------------------------------------------------------------
// A-side: fused L2-normalize + fp16 two-limb split into pre-swizzled tiles.
// One CTA per row (256 threads, 4 elems/thread).
//   xn = x / ||row||;  hi = fp16(xn);  lo = fp16((xn - hi) * 2048)
// Tile: tile = (row>>7)*KCHUNKS + (k>>6); swizzled (row&127)*128 + (k&63)*2.
// ---------------------------------------------------------------------------
__global__ void __launch_bounds__(256)
convert_a(const float4* __restrict__ src, char* __restrict__ hi, char* __restrict__ lo)
{
    const int row = blockIdx.x;
    const int tid = threadIdx.x;
    const float4 v = src[(size_t)row * 256 + tid];
    const float x[4] = {v.x, v.y, v.z, v.w};

    __shared__ float red[256];
    red[tid] = x[0]*x[0] + x[1]*x[1] + x[2]*x[2] + x[3]*x[3];
    __syncthreads();
#pragma unroll
    for (int off = 128; off > 0; off >>= 1) {
        if (tid < off) red[tid] += red[tid + off];
        __syncthreads();
    }
    const float inv = 1.0f / fmaxf(sqrtf(red[0]), 1e-12f);

    unsigned short h[4], l[4];
#pragma unroll
    for (int j = 0; j < 4; ++j) {
        const float xn = x[j] * inv;
        const __half hb = __float2half_rn(xn);
        const float r = (xn - __half2float(hb)) * LO_SCALE;
        h[j] = __half_as_ushort(hb);
        l[j] = __half_as_ushort(__float2half_rn(r));
    }

    const int k = tid * 4;
    const int tile = (row >> 7) * KCHUNKS + (k >> 6);
    uint32_t off = (uint32_t)((row & 127) * 128 + (k & 63) * 2);
    off ^= (off >> 3) & 0x70;

    uint2 ph, pl;
    ph.x = (uint32_t)h[0] | ((uint32_t)h[1] << 16);
    ph.y = (uint32_t)h[2] | ((uint32_t)h[3] << 16);
    pl.x = (uint32_t)l[0] | ((uint32_t)l[1] << 16);
    pl.y = (uint32_t)l[2] | ((uint32_t)l[3] << 16);
    *(uint2*)(hi + (size_t)tile * TILE_B + off) = ph;
    *(uint2*)(lo + (size_t)tile * TILE_B + off) = pl;
}

// ---------------------------------------------------------------------------
// B-side: fp16 hi limb only, pre-swizzled tiles. Elementwise (4 per thread).
// ---------------------------------------------------------------------------
__global__ void __launch_bounds__(256)
convert_b(const float4* __restrict__ src, char* __restrict__ hi)
{
    const size_t i4 = (size_t)blockIdx.x * 256 + threadIdx.x;
    const int row = (int)(i4 >> 8);
    const int k   = ((int)i4 & 255) * 4;
    const float4 v = src[i4];
    const float x[4] = {v.x, v.y, v.z, v.w};

    unsigned short h[4];
#pragma unroll
    for (int j = 0; j < 4; ++j)
        h[j] = __half_as_ushort(__float2half_rn(x[j]));

    const int tile = (row >> 7) * KCHUNKS + (k >> 6);
    uint32_t off = (uint32_t)((row & 127) * 128 + (k & 63) * 2);
    off ^= (off >> 3) & 0x70;

    uint2 ph;
    ph.x = (uint32_t)h[0] | ((uint32_t)h[1] << 16);
    ph.y = (uint32_t)h[2] | ((uint32_t)h[3] << 16);
    *(uint2*)(hi + (size_t)tile * TILE_B + off) = ph;
}

// ---------------------------------------------------------------------------
// Similarity GEMM, fp16 two-limb A x one-limb B (~fp32 accuracy):
//   S[m,n] = Ahi.Bhi (f32 accum) + (Alo.Bhi) (f16 accum) * 2^-11
// CTA tile 128x128 (8 warps, 4M x 2N). K chunks of 64 fp16.
// cp.async.bulk (3 x 16KB per stage) + mbarrier expect_tx, 4-stage pipeline.
// ---------------------------------------------------------------------------
__global__ void __launch_bounds__(256, 1)
sim_mma(const char* __restrict__ Ah, const char* __restrict__ Al,
        const char* __restrict__ Bh, float* __restrict__ S)
{
    extern __shared__ char smem_raw[];
    const uint32_t sbase = sm_u32(smem_raw);
    const uint32_t mbar0 = sbase;                          // 4 x 8B mbarriers
    const uint32_t data0 = (sbase + 32u + 1023u) & ~1023u;

    const int tid = threadIdx.x;
    const int w = tid >> 5, l = tid & 31;
    const int wm = w & 3;
    const int wn = w >> 2;
    const int mb = blockIdx.x;    // 0..7
    const int nb = blockIdx.y;    // 0..255

    if (tid == 0) {
#pragma unroll
        for (int s = 0; s < NSTAGES; ++s)
            asm volatile("mbarrier.init.shared.b64 [%0], 1;" :: "r"(mbar0 + s * 8) : "memory");
    }
    __syncthreads();

    const int rowA  = wm * 32 + (l & 15);
    const uint32_t hA = (uint32_t)(l >> 4) << 4;
    const int rowB0 = wn * 64 + (l & 7) + ((l & 16) >> 1);
    const uint32_t hB = (uint32_t)(l & 8) << 1;
    const uint32_t swz = (uint32_t)(l & 7) << 4;

    float    acc[2][8][4];     // main: Ahi.Bhi, fp32
    uint32_t accC[2][8][2];    // corr: Alo.Bhi, fp16x2 pairs
#pragma unroll
    for (int i = 0; i < 2; ++i)
#pragma unroll
        for (int j = 0; j < 8; ++j) {
#pragma unroll
            for (int q = 0; q < 4; ++q) acc[i][j][q] = 0.f;
            accC[i][j][0] = 0u; accC[i][j][1] = 0u;
        }

    auto issue = [&](int kc, int s) {
        const uint32_t d = data0 + s * STAGE_B;
        const uint32_t bar = mbar0 + s * 8;
        const size_t aoff = ((size_t)mb * KCHUNKS + kc) * TILE_B;
        const size_t boff = ((size_t)nb * KCHUNKS + kc) * TILE_B;
        asm volatile("mbarrier.arrive.expect_tx.shared.b64 _, [%0], %1;"
                     :: "r"(bar), "r"((uint32_t)STAGE_B) : "memory");
        BULK_LOAD(d,              Ah + aoff, bar);
        BULK_LOAD(d + 1 * TILE_B, Al + aoff, bar);
        BULK_LOAD(d + 2 * TILE_B, Bh + boff, bar);
    };

    if (tid == 0) { issue(0, 0); issue(1, 1); issue(2, 2); }

    int ph[NSTAGES] = {0, 0, 0, 0};

    for (int kc = 0; kc < KCHUNKS; ++kc) {
        const int s = kc % NSTAGES;
        mbar_wait(mbar0 + s * 8, ph[s]);
        ph[s] ^= 1;
        __syncthreads();   // all warps done with the stage being reissued (chunk kc-1)
        if (tid == 0 && kc + 3 < KCHUNKS) issue(kc + 3, (kc + 3) % NSTAGES);

        const uint32_t aHb = data0 + s * STAGE_B;
        const uint32_t aLb = aHb + 1 * TILE_B;
        const uint32_t bHb = aHb + 2 * TILE_B;

#pragma unroll
        for (int ks = 0; ks < 4; ++ks) {
            uint32_t ah[2][4], al[2][4];
#pragma unroll
            for (int mi = 0; mi < 2; ++mi) {
                const uint32_t pa =
                    ((uint32_t)((rowA + mi * 16) * 128) + (uint32_t)(ks * 32) + hA) ^ swz;
                LDSM4(ah[mi], aHb + pa);
                LDSM4(al[mi], aLb + pa);
            }
#pragma unroll
            for (int nk = 0; nk < 4; ++nk) {
                const uint32_t pb =
                    ((uint32_t)((rowB0 + nk * 16) * 128) + (uint32_t)(ks * 32) + hB) ^ swz;
                uint32_t bh[4];
                LDSM4(bh, bHb + pb);
#pragma unroll
                for (int mi = 0; mi < 2; ++mi) {
                    MMA_F16_F32(acc[mi][nk * 2 + 0], ah[mi], bh[0], bh[1]);
                    MMA_F16_F32(acc[mi][nk * 2 + 1], ah[mi], bh[2], bh[3]);
                    MMA_F16_F16(accC[mi][nk * 2 + 0], al[mi], bh[0], bh[1]);
                    MMA_F16_F16(accC[mi][nk * 2 + 1], al[mi], bh[2], bh[3]);
                }
            }
        }
    }

    // epilogue: S = main + corr * 2^-11
    const float cs = 1.0f / LO_SCALE;
    const int gm0 = mb * 128 + wm * 32 + (l >> 2);
    const int gn0 = nb * 128 + wn * 64 + (l & 3) * 2;
#pragma unroll
    for (int mi = 0; mi < 2; ++mi) {
#pragma unroll
        for (int nk = 0; nk < 4; ++nk) {
#pragma unroll
            for (int hf = 0; hf < 2; ++hf) {
                const float* a = acc[mi][nk * 2 + hf];
                const uint32_t* c = accC[mi][nk * 2 + hf];
                const __half2 c0 = *(const __half2*)&c[0];   // row r,   cols n,n+1
                const __half2 c1 = *(const __half2*)&c[1];   // row r+8, cols n,n+1
                float* p = S + (size_t)(gm0 + mi * 16) * NCONCEPT + gn0 + nk * 16 + hf * 8;
                float2 v0, v1;
                v0.x = a[0] + __half2float(__low2half(c0))  * cs;
                v0.y = a[1] + __half2float(__high2half(c0)) * cs;
                v1.x = a[2] + __half2float(__low2half(c1))  * cs;
                v1.y = a[3] + __half2float(__high2half(c1)) * cs;
                *(float2*)p = v0;
                *(float2*)(p + (size_t)8 * NCONCEPT) = v1;
            }
        }
    }
}

// ---------------------------------------------------------------------------
// Per-row softmax(sim * INV_T) + argmax. One CTA (256 threads) per row.
// float4-vectorized loads/stores.
// ---------------------------------------------------------------------------
__global__ void __launch_bounds__(256)
softmax_row(const float* __restrict__ S,
            float* __restrict__ act,
            float* __restrict__ bidx)
{
    const int row = blockIdx.x;
    const int tid = threadIdx.x;
    const float4* s4 = (const float4*)(S + (size_t)row * NCONCEPT);

    float m = -INFINITY;
    float Z = 0.f;
    int   bi = 0;

    for (int j = tid; j < NCONCEPT / 4; j += 256) {
        const float4 v = s4[j];
        const float x[4] = {v.x, v.y, v.z, v.w};
#pragma unroll
        for (int q = 0; q < 4; ++q) {
            if (x[q] > m) {
                Z = Z * __expf((m - x[q]) * INV_T) + 1.0f;
                m = x[q];
                bi = j * 4 + q;
            } else {
                Z += __expf((x[q] - m) * INV_T);
            }
        }
    }

    __shared__ float sm[256];
    __shared__ float sz[256];
    __shared__ int   si[256];
    sm[tid] = m; sz[tid] = Z; si[tid] = bi;
    __syncthreads();

#pragma unroll
    for (int off = 128; off > 0; off >>= 1) {
        if (tid < off) {
            const float m1 = sm[tid],       z1 = sz[tid];
            const float m2 = sm[tid + off], z2 = sz[tid + off];
            const int   i1 = si[tid],       i2 = si[tid + off];
            if (m2 > m1 || (m2 == m1 && i2 < i1)) {
                sm[tid] = m2;
                sz[tid] = z2 + z1 * __expf((m1 - m2) * INV_T);
                si[tid] = i2;
            } else {
                sz[tid] = z1 + z2 * __expf((m2 - m1) * INV_T);
            }
        }
        __syncthreads();
    }

    const float M    = sm[0];
    const float invZ = 1.0f / sz[0];
    float4* a4 = (float4*)(act + (size_t)row * NCONCEPT);
    for (int j = tid; j < NCONCEPT / 4; j += 256) {
        const float4 v = s4[j];
        float4 o;
        o.x = __expf((v.x - M) * INV_T) * invZ;
        o.y = __expf((v.y - M) * INV_T) * invZ;
        o.z = __expf((v.z - M) * INV_T) * invZ;
        o.w = __expf((v.w - M) * INV_T) * invZ;
        a4[j] = o;
    }

    if (tid == 0) bidx[row] = (float)si[0];
}

// ---------------------------------------------------------------------------
extern "C" void kernel_launch(void* const* d_in, const int* in_sizes, int n_in,
                              void* d_out, int out_size)
{
    const float* features   = (const float*)d_in[0];  // [1024, 1024]
    const float* W          = (const float*)d_in[1];  // [1024, 1024]
    const float* b          = (const float*)d_in[2];  // [1024]
    const float* prototypes = (const float*)d_in[3];  // [32768, 1024]

    float* out  = (float*)d_out;
    float* act  = out;                                   // [1024, 32768]
    float* bidx = out + (size_t)BATCH * NCONCEPT;        // [1024] as float

    float *pP = nullptr, *pS = nullptr;
    char *pAh = nullptr, *pAl = nullptr, *pBh = nullptr;
    cudaGetSymbolAddress((void**)&pP,  g_P);
    cudaGetSymbolAddress((void**)&pS,  g_S);
    cudaGetSymbolAddress((void**)&pAh, g_Ah);
    cudaGetSymbolAddress((void**)&pAl, g_Al);
    cudaGetSymbolAddress((void**)&pBh, g_Bh);

    cudaFuncSetAttribute(sim_mma, cudaFuncAttributeMaxDynamicSharedMemorySize, SMEM_TOTAL);

    // 1) projection: P = features @ W^T + b   [1024, 1024] (fp32)
    sgemm128_nt<true><<<dim3(FDIM / 128, BATCH / 128), 256>>>(
        features, W, b, pP, BATCH, FDIM, FDIM);

    // 2) A: fused L2-normalize + fp16 two-limb split; B: fp16 hi limb
    convert_a<<<BATCH, 256>>>((const float4*)pP, pAh, pAl);
    convert_b<<<(NCONCEPT * FDIM / 4) / 256, 256>>>((const float4*)prototypes, pBh);

    // 3) similarities via fp16 two-term mma.sync
    sim_mma<<<dim3(BATCH / 128, NCONCEPT / 128), 256, SMEM_TOTAL>>>(
        pAh, pAl, pBh, pS);

    // 4) per-row softmax(S/T) + argmax
    softmax_row<<<BATCH, 256>>>(pS, act, bidx);
}

// round 6
// speedup vs baseline: 3.5568x; 1.1328x over previous
#include <cuda_runtime.h>
#include <cuda_fp16.h>
#include <math.h>
#include <stdint.h>

// Problem constants
#define BATCH     1024
#define FDIM      1024
#define NCONCEPT  32768
#define INV_T     10.0f   // 1 / 0.1

#define TILE_B    16384          // one 128x64-fp16 swizzled tile (128 rows * 128 B)
#define KCHUNKS   16             // 1024 / 64
#define LO_SCALE  2048.0f        // 2^11: keeps lo limbs in fp16 normal range

// sim pipeline: Ahi, Alo, Bhi per stage = 48 KB, 4 stages
#define STAGE_S   (3 * TILE_B)
#define NSTAGES_S 4
#define SMEM_SIM  (1024 + NSTAGES_S * STAGE_S)
// proj pipeline: Fhi, Flo, Whi, Wlo per stage = 64 KB, 3 stages
#define STAGE_P   (4 * TILE_B)
#define NSTAGES_P 3
#define SMEM_PROJ (1024 + NSTAGES_P * STAGE_P)

// ---------------- scratch (device globals; no allocation allowed) ----------
__device__ float g_P[BATCH * FDIM];                      // projection output
__device__ float g_S[(size_t)BATCH * NCONCEPT];          // similarities (134 MB)
__device__ __align__(256) char g_Fh[(size_t)BATCH * FDIM * 2];     // features limbs
__device__ __align__(256) char g_Fl[(size_t)BATCH * FDIM * 2];
__device__ __align__(256) char g_Wh[(size_t)FDIM * FDIM * 2];      // W limbs
__device__ __align__(256) char g_Wl[(size_t)FDIM * FDIM * 2];
__device__ __align__(256) char g_Ah[(size_t)BATCH * FDIM * 2];     // normalized P limbs
__device__ __align__(256) char g_Al[(size_t)BATCH * FDIM * 2];
__device__ __align__(256) char g_Bh[(size_t)NCONCEPT * FDIM * 2];  // prototypes hi limb

// ---------------------------------------------------------------------------
// PTX helpers (baseline ISA only)
// ---------------------------------------------------------------------------
__device__ __forceinline__ uint32_t sm_u32(const void* p) {
    uint32_t a;
    asm("{ .reg .u64 t; cvta.to.shared.u64 t, %1; cvt.u32.u64 %0, t; }"
        : "=r"(a) : "l"(p));
    return a;
}

__device__ __forceinline__ void mbar_wait(uint32_t addr, int phase) {
    asm volatile(
        "{\n\t.reg .pred P;\n\t"
        "WL_%=:\n\t"
        "mbarrier.try_wait.parity.acquire.cta.shared::cta.b64 P, [%0], %1, 0x989680;\n\t"
        "@P bra.uni WD_%=;\n\t"
        "bra.uni WL_%=;\n\t"
        "WD_%=:\n\t}"
        :: "r"(addr), "r"((uint32_t)phase) : "memory");
}

#define LDSM4(R, addr) \
    asm volatile("ldmatrix.sync.aligned.m8n8.x4.shared.b16 {%0,%1,%2,%3}, [%4];" \
        : "=r"((R)[0]), "=r"((R)[1]), "=r"((R)[2]), "=r"((R)[3]) : "r"(addr))

#define MMA_F16_F32(C, A, b0_, b1_) \
    asm volatile("mma.sync.aligned.m16n8k16.row.col.f32.f16.f16.f32 " \
        "{%0,%1,%2,%3}, {%4,%5,%6,%7}, {%8,%9}, {%0,%1,%2,%3};" \
        : "+f"((C)[0]), "+f"((C)[1]), "+f"((C)[2]), "+f"((C)[3]) \
        : "r"((A)[0]), "r"((A)[1]), "r"((A)[2]), "r"((A)[3]), "r"(b0_), "r"(b1_))

#define MMA_F16_F16(C, A, b0_, b1_) \
    asm volatile("mma.sync.aligned.m16n8k16.row.col.f16.f16.f16.f16 " \
        "{%0,%1}, {%2,%3,%4,%5}, {%6,%7}, {%0,%1};" \
        : "+r"((C)[0]), "+r"((C)[1]) \
        : "r"((A)[0]), "r"((A)[1]), "r"((A)[2]), "r"((A)[3]), "r"(b0_), "r"(b1_))

#define BULK_LOAD(dst, src, bar) \
    asm volatile("cp.async.bulk.shared::cluster.global.mbarrier::complete_tx::bytes " \
        "[%0], [%1], %2, [%3];" \
        :: "r"(dst), "l"(src), "r"((uint32_t)TILE_B), "r"(bar) : "memory")

// ---------------------------------------------------------------------------
// fp32 -> fp16 two-limb split into pre-swizzled 128x64 tiles (no norm).
// hi = fp16(x); lo = fp16((x - hi) * 2048). 4 elems/thread.
// ---------------------------------------------------------------------------
__global__ void __launch_bounds__(256)
convert_split2(const float4* __restrict__ src, char* __restrict__ hi, char* __restrict__ lo)
{
    const size_t i4 = (size_t)blockIdx.x * 256 + threadIdx.x;
    const int row = (int)(i4 >> 8);
    const int k   = ((int)i4 & 255) * 4;
    const float4 v = src[i4];
    const float x[4] = {v.x, v.y, v.z, v.w};

    unsigned short h[4], l[4];
#pragma unroll
    for (int j = 0; j < 4; ++j) {
        const __half hb = __float2half_rn(x[j]);
        const float r = (x[j] - __half2float(hb)) * LO_SCALE;
        h[j] = __half_as_ushort(hb);
        l[j] = __half_as_ushort(__float2half_rn(r));
    }

    const int tile = (row >> 7) * KCHUNKS + (k >> 6);
    uint32_t off = (uint32_t)((row & 127) * 128 + (k & 63) * 2);
    off ^= (off >> 3) & 0x70;

    uint2 ph, pl;
    ph.x = (uint32_t)h[0] | ((uint32_t)h[1] << 16);
    ph.y = (uint32_t)h[2] | ((uint32_t)h[3] << 16);
    pl.x = (uint32_t)l[0] | ((uint32_t)l[1] << 16);
    pl.y = (uint32_t)l[2] | ((uint32_t)l[3] << 16);
    *(uint2*)(hi + (size_t)tile * TILE_B + off) = ph;
    *(uint2*)(lo + (size_t)tile * TILE_B + off) = pl;
}

// ---------------------------------------------------------------------------
// A-side: fused L2-normalize + fp16 two-limb split. One CTA per row.
// ---------------------------------------------------------------------------
__global__ void __launch_bounds__(256)
convert_a(const float4* __restrict__ src, char* __restrict__ hi, char* __restrict__ lo)
{
    const int row = blockIdx.x;
    const int tid = threadIdx.x;
    const float4 v = src[(size_t)row * 256 + tid];
    const float x[4] = {v.x, v.y, v.z, v.w};

    __shared__ float red[256];
    red[tid] = x[0]*x[0] + x[1]*x[1] + x[2]*x[2] + x[3]*x[3];
    __syncthreads();
#pragma unroll
    for (int off = 128; off > 0; off >>= 1) {
        if (tid < off) red[tid] += red[tid + off];
        __syncthreads();
    }
    const float inv = 1.0f / fmaxf(sqrtf(red[0]), 1e-12f);

    unsigned short h[4], l[4];
#pragma unroll
    for (int j = 0; j < 4; ++j) {
        const float xn = x[j] * inv;
        const __half hb = __float2half_rn(xn);
        const float r = (xn - __half2float(hb)) * LO_SCALE;
        h[j] = __half_as_ushort(hb);
        l[j] = __half_as_ushort(__float2half_rn(r));
    }

    const int k = tid * 4;
    const int tile = (row >> 7) * KCHUNKS + (k >> 6);
    uint32_t off = (uint32_t)((row & 127) * 128 + (k & 63) * 2);
    off ^= (off >> 3) & 0x70;

    uint2 ph, pl;
    ph.x = (uint32_t)h[0] | ((uint32_t)h[1] << 16);
    ph.y = (uint32_t)h[2] | ((uint32_t)h[3] << 16);
    pl.x = (uint32_t)l[0] | ((uint32_t)l[1] << 16);
    pl.y = (uint32_t)l[2] | ((uint32_t)l[3] << 16);
    *(uint2*)(hi + (size_t)tile * TILE_B + off) = ph;
    *(uint2*)(lo + (size_t)tile * TILE_B + off) = pl;
}

// ---------------------------------------------------------------------------
// B-side: fp16 hi limb only, pre-swizzled tiles.
// ---------------------------------------------------------------------------
__global__ void __launch_bounds__(256)
convert_b(const float4* __restrict__ src, char* __restrict__ hi)
{
    const size_t i4 = (size_t)blockIdx.x * 256 + threadIdx.x;
    const int row = (int)(i4 >> 8);
    const int k   = ((int)i4 & 255) * 4;
    const float4 v = src[i4];
    const float x[4] = {v.x, v.y, v.z, v.w};

    unsigned short h[4];
#pragma unroll
    for (int j = 0; j < 4; ++j)
        h[j] = __half_as_ushort(__float2half_rn(x[j]));

    const int tile = (row >> 7) * KCHUNKS + (k >> 6);
    uint32_t off = (uint32_t)((row & 127) * 128 + (k & 63) * 2);
    off ^= (off >> 3) & 0x70;

    uint2 ph;
    ph.x = (uint32_t)h[0] | ((uint32_t)h[1] << 16);
    ph.y = (uint32_t)h[2] | ((uint32_t)h[3] << 16);
    *(uint2*)(hi + (size_t)tile * TILE_B + off) = ph;
}

// ---------------------------------------------------------------------------
// Projection GEMM, fp16 3-term limbs (~fp32):
//   P[m,n] = Fhi.Whi (f32) + (Fhi.Wlo + Flo.Whi) (f16) * 2^-11 + bias[n]
// CTA 128x128, 16 warps (4M x 4N, warp tile 32x32). 3-stage 64KB pipeline.
// ---------------------------------------------------------------------------
__global__ void __launch_bounds__(512, 1)
proj_mma(const char* __restrict__ Fh, const char* __restrict__ Fl,
         const char* __restrict__ Wh, const char* __restrict__ Wl,
         const float* __restrict__ bias, float* __restrict__ P)
{
    extern __shared__ char smem_raw[];
    const uint32_t sbase = sm_u32(smem_raw);
    const uint32_t mbar0 = sbase;
    const uint32_t data0 = (sbase + 32u + 1023u) & ~1023u;

    const int tid = threadIdx.x;
    const int w = tid >> 5, l = tid & 31;
    const int wm = w & 3;
    const int wn = w >> 2;        // 0..3
    const int mb = blockIdx.x;    // 0..7
    const int nb = blockIdx.y;    // 0..7

    if (tid == 0) {
#pragma unroll
        for (int s = 0; s < NSTAGES_P; ++s)
            asm volatile("mbarrier.init.shared.b64 [%0], 1;" :: "r"(mbar0 + s * 8) : "memory");
    }
    __syncthreads();

    const int rowA  = wm * 32 + (l & 15);
    const uint32_t hA = (uint32_t)(l >> 4) << 4;
    const int rowB0 = wn * 32 + (l & 7) + ((l & 16) >> 1);
    const uint32_t hB = (uint32_t)(l & 8) << 1;
    const uint32_t swz = (uint32_t)(l & 7) << 4;

    float    acc[2][4][4];
    uint32_t accC[2][4][2];
#pragma unroll
    for (int i = 0; i < 2; ++i)
#pragma unroll
        for (int j = 0; j < 4; ++j) {
#pragma unroll
            for (int q = 0; q < 4; ++q) acc[i][j][q] = 0.f;
            accC[i][j][0] = 0u; accC[i][j][1] = 0u;
        }

    auto issue = [&](int kc, int s) {
        const uint32_t d = data0 + s * STAGE_P;
        const uint32_t bar = mbar0 + s * 8;
        const size_t aoff = ((size_t)mb * KCHUNKS + kc) * TILE_B;
        const size_t boff = ((size_t)nb * KCHUNKS + kc) * TILE_B;
        asm volatile("mbarrier.arrive.expect_tx.shared.b64 _, [%0], %1;"
                     :: "r"(bar), "r"((uint32_t)STAGE_P) : "memory");
        BULK_LOAD(d,              Fh + aoff, bar);
        BULK_LOAD(d + 1 * TILE_B, Fl + aoff, bar);
        BULK_LOAD(d + 2 * TILE_B, Wh + boff, bar);
        BULK_LOAD(d + 3 * TILE_B, Wl + boff, bar);
    };

    if (tid == 0) { issue(0, 0); issue(1, 1); }

    int ph[NSTAGES_P] = {0, 0, 0};

    for (int kc = 0; kc < KCHUNKS; ++kc) {
        const int s = kc % NSTAGES_P;
        mbar_wait(mbar0 + s * 8, ph[s]);
        ph[s] ^= 1;
        __syncthreads();
        if (tid == 0 && kc + 2 < KCHUNKS) issue(kc + 2, (kc + 2) % NSTAGES_P);

        const uint32_t aHb = data0 + s * STAGE_P;
        const uint32_t aLb = aHb + 1 * TILE_B;
        const uint32_t bHb = aHb + 2 * TILE_B;
        const uint32_t bLb = aHb + 3 * TILE_B;

#pragma unroll
        for (int ks = 0; ks < 4; ++ks) {
            uint32_t ah[2][4], al[2][4];
#pragma unroll
            for (int mi = 0; mi < 2; ++mi) {
                const uint32_t pa =
                    ((uint32_t)((rowA + mi * 16) * 128) + (uint32_t)(ks * 32) + hA) ^ swz;
                LDSM4(ah[mi], aHb + pa);
                LDSM4(al[mi], aLb + pa);
            }
#pragma unroll
            for (int nk = 0; nk < 2; ++nk) {
                const uint32_t pb =
                    ((uint32_t)((rowB0 + nk * 16) * 128) + (uint32_t)(ks * 32) + hB) ^ swz;
                uint32_t bh[4], bl[4];
                LDSM4(bh, bHb + pb);
                LDSM4(bl, bLb + pb);
#pragma unroll
                for (int mi = 0; mi < 2; ++mi) {
                    MMA_F16_F32(acc[mi][nk * 2 + 0], ah[mi], bh[0], bh[1]);
                    MMA_F16_F32(acc[mi][nk * 2 + 1], ah[mi], bh[2], bh[3]);
                    MMA_F16_F16(accC[mi][nk * 2 + 0], ah[mi], bl[0], bl[1]);
                    MMA_F16_F16(accC[mi][nk * 2 + 1], ah[mi], bl[2], bl[3]);
                    MMA_F16_F16(accC[mi][nk * 2 + 0], al[mi], bh[0], bh[1]);
                    MMA_F16_F16(accC[mi][nk * 2 + 1], al[mi], bh[2], bh[3]);
                }
            }
        }
    }

    const float cs = 1.0f / LO_SCALE;
    const int gm0 = mb * 128 + wm * 32 + (l >> 2);
    const int gn0 = nb * 128 + wn * 32 + (l & 3) * 2;
#pragma unroll
    for (int mi = 0; mi < 2; ++mi) {
#pragma unroll
        for (int nk = 0; nk < 2; ++nk) {
#pragma unroll
            for (int hf = 0; hf < 2; ++hf) {
                const int n = gn0 + nk * 16 + hf * 8;
                const float b0 = bias[n], b1 = bias[n + 1];
                const float* a = acc[mi][nk * 2 + hf];
                const uint32_t* c = accC[mi][nk * 2 + hf];
                const __half2 c0 = *(const __half2*)&c[0];
                const __half2 c1 = *(const __half2*)&c[1];
                float* p = P + (size_t)(gm0 + mi * 16) * FDIM + n;
                float2 v0, v1;
                v0.x = a[0] + __half2float(__low2half(c0))  * cs + b0;
                v0.y = a[1] + __half2float(__high2half(c0)) * cs + b1;
                v1.x = a[2] + __half2float(__low2half(c1))  * cs + b0;
                v1.y = a[3] + __half2float(__high2half(c1)) * cs + b1;
                *(float2*)p = v0;
                *(float2*)(p + (size_t)8 * FDIM) = v1;
            }
        }
    }
}

// ---------------------------------------------------------------------------
// Similarity GEMM, fp16 two-limb A x one-limb B (~fp32 accuracy):
//   S[m,n] = Ahi.Bhi (f32) + (Alo.Bhi) (f16) * 2^-11
// CTA 128x128, 16 warps (4M x 4N, warp tile 32x32). 4-stage 48KB pipeline.
// ---------------------------------------------------------------------------
__global__ void __launch_bounds__(512, 1)
sim_mma(const char* __restrict__ Ah, const char* __restrict__ Al,
        const char* __restrict__ Bh, float* __restrict__ S)
{
    extern __shared__ char smem_raw[];
    const uint32_t sbase = sm_u32(smem_raw);
    const uint32_t mbar0 = sbase;
    const uint32_t data0 = (sbase + 32u + 1023u) & ~1023u;

    const int tid = threadIdx.x;
    const int w = tid >> 5, l = tid & 31;
    const int wm = w & 3;
    const int wn = w >> 2;        // 0..3
    const int mb = blockIdx.x;    // 0..7
    const int nb = blockIdx.y;    // 0..255

    if (tid == 0) {
#pragma unroll
        for (int s = 0; s < NSTAGES_S; ++s)
            asm volatile("mbarrier.init.shared.b64 [%0], 1;" :: "r"(mbar0 + s * 8) : "memory");
    }
    __syncthreads();

    const int rowA  = wm * 32 + (l & 15);
    const uint32_t hA = (uint32_t)(l >> 4) << 4;
    const int rowB0 = wn * 32 + (l & 7) + ((l & 16) >> 1);
    const uint32_t hB = (uint32_t)(l & 8) << 1;
    const uint32_t swz = (uint32_t)(l & 7) << 4;

    float    acc[2][4][4];
    uint32_t accC[2][4][2];
#pragma unroll
    for (int i = 0; i < 2; ++i)
#pragma unroll
        for (int j = 0; j < 4; ++j) {
#pragma unroll
            for (int q = 0; q < 4; ++q) acc[i][j][q] = 0.f;
            accC[i][j][0] = 0u; accC[i][j][1] = 0u;
        }

    auto issue = [&](int kc, int s) {
        const uint32_t d = data0 + s * STAGE_S;
        const uint32_t bar = mbar0 + s * 8;
        const size_t aoff = ((size_t)mb * KCHUNKS + kc) * TILE_B;
        const size_t boff = ((size_t)nb * KCHUNKS + kc) * TILE_B;
        asm volatile("mbarrier.arrive.expect_tx.shared.b64 _, [%0], %1;"
                     :: "r"(bar), "r"((uint32_t)STAGE_S) : "memory");
        BULK_LOAD(d,              Ah + aoff, bar);
        BULK_LOAD(d + 1 * TILE_B, Al + aoff, bar);
        BULK_LOAD(d + 2 * TILE_B, Bh + boff, bar);
    };

    if (tid == 0) { issue(0, 0); issue(1, 1); issue(2, 2); }

    int ph[NSTAGES_S] = {0, 0, 0, 0};

    for (int kc = 0; kc < KCHUNKS; ++kc) {
        const int s = kc % NSTAGES_S;
        mbar_wait(mbar0 + s * 8, ph[s]);
        ph[s] ^= 1;
        __syncthreads();
        if (tid == 0 && kc + 3 < KCHUNKS) issue(kc + 3, (kc + 3) % NSTAGES_S);

        const uint32_t aHb = data0 + s * STAGE_S;
        const uint32_t aLb = aHb + 1 * TILE_B;
        const uint32_t bHb = aHb + 2 * TILE_B;

#pragma unroll
        for (int ks = 0; ks < 4; ++ks) {
            uint32_t ah[2][4], al[2][4];
#pragma unroll
            for (int mi = 0; mi < 2; ++mi) {
                const uint32_t pa =
                    ((uint32_t)((rowA + mi * 16) * 128) + (uint32_t)(ks * 32) + hA) ^ swz;
                LDSM4(ah[mi], aHb + pa);
                LDSM4(al[mi], aLb + pa);
            }
#pragma unroll
            for (int nk = 0; nk < 2; ++nk) {
                const uint32_t pb =
                    ((uint32_t)((rowB0 + nk * 16) * 128) + (uint32_t)(ks * 32) + hB) ^ swz;
                uint32_t bh[4];
                LDSM4(bh, bHb + pb);
#pragma unroll
                for (int mi = 0; mi < 2; ++mi) {
                    MMA_F16_F32(acc[mi][nk * 2 + 0], ah[mi], bh[0], bh[1]);
                    MMA_F16_F32(acc[mi][nk * 2 + 1], ah[mi], bh[2], bh[3]);
                    MMA_F16_F16(accC[mi][nk * 2 + 0], al[mi], bh[0], bh[1]);
                    MMA_F16_F16(accC[mi][nk * 2 + 1], al[mi], bh[2], bh[3]);
                }
            }
        }
    }

    const float cs = 1.0f / LO_SCALE;
    const int gm0 = mb * 128 + wm * 32 + (l >> 2);
    const int gn0 = nb * 128 + wn * 32 + (l & 3) * 2;
#pragma unroll
    for (int mi = 0; mi < 2; ++mi) {
#pragma unroll
        for (int nk = 0; nk < 2; ++nk) {
#pragma unroll
            for (int hf = 0; hf < 2; ++hf) {
                const float* a = acc[mi][nk * 2 + hf];
                const uint32_t* c = accC[mi][nk * 2 + hf];
                const __half2 c0 = *(const __half2*)&c[0];
                const __half2 c1 = *(const __half2*)&c[1];
                float* p = S + (size_t)(gm0 + mi * 16) * NCONCEPT + gn0 + nk * 16 + hf * 8;
                float2 v0, v1;
                v0.x = a[0] + __half2float(__low2half(c0))  * cs;
                v0.y = a[1] + __half2float(__high2half(c0)) * cs;
                v1.x = a[2] + __half2float(__low2half(c1))  * cs;
                v1.y = a[3] + __half2float(__high2half(c1)) * cs;
                *(float2*)p = v0;
                *(float2*)(p + (size_t)8 * NCONCEPT) = v1;
            }
        }
    }
}

// ---------------------------------------------------------------------------
// Per-row softmax(sim * INV_T) + argmax. One CTA (256 threads) per row.
// ---------------------------------------------------------------------------
__global__ void __launch_bounds__(256)
softmax_row(const float* __restrict__ S,
            float* __restrict__ act,
            float* __restrict__ bidx)
{
    const int row = blockIdx.x;
    const int tid = threadIdx.x;
    const float4* s4 = (const float4*)(S + (size_t)row * NCONCEPT);

    float m = -INFINITY;
    float Z = 0.f;
    int   bi = 0;

    for (int j = tid; j < NCONCEPT / 4; j += 256) {
        const float4 v = s4[j];
        const float x[4] = {v.x, v.y, v.z, v.w};
#pragma unroll
        for (int q = 0; q < 4; ++q) {
            if (x[q] > m) {
                Z = Z * __expf((m - x[q]) * INV_T) + 1.0f;
                m = x[q];
                bi = j * 4 + q;
            } else {
                Z += __expf((x[q] - m) * INV_T);
            }
        }
    }

    __shared__ float sm[256];
    __shared__ float sz[256];
    __shared__ int   si[256];
    sm[tid] = m; sz[tid] = Z; si[tid] = bi;
    __syncthreads();

#pragma unroll
    for (int off = 128; off > 0; off >>= 1) {
        if (tid < off) {
            const float m1 = sm[tid],       z1 = sz[tid];
            const float m2 = sm[tid + off], z2 = sz[tid + off];
            const int   i1 = si[tid],       i2 = si[tid + off];
            if (m2 > m1 || (m2 == m1 && i2 < i1)) {
                sm[tid] = m2;
                sz[tid] = z2 + z1 * __expf((m1 - m2) * INV_T);
                si[tid] = i2;
            } else {
                sz[tid] = z1 + z2 * __expf((m2 - m1) * INV_T);
            }
        }
        __syncthreads();
    }

    const float M    = sm[0];
    const float invZ = 1.0f / sz[0];
    float4* a4 = (float4*)(act + (size_t)row * NCONCEPT);
    for (int j = tid; j < NCONCEPT / 4; j += 256) {
        const float4 v = s4[j];
        float4 o;
        o.x = __expf((v.x - M) * INV_T) * invZ;
        o.y = __expf((v.y - M) * INV_T) * invZ;
        o.z = __expf((v.z - M) * INV_T) * invZ;
        o.w = __expf((v.w - M) * INV_T) * invZ;
        a4[j] = o;
    }

    if (tid == 0) bidx[row] = (float)si[0];
}

// ---------------------------------------------------------------------------
extern "C" void kernel_launch(void* const* d_in, const int* in_sizes, int n_in,
                              void* d_out, int out_size)
{
    const float* features   = (const float*)d_in[0];  // [1024, 1024]
    const float* W          = (const float*)d_in[1];  // [1024, 1024]
    const float* b          = (const float*)d_in[2];  // [1024]
    const float* prototypes = (const float*)d_in[3];  // [32768, 1024]

    float* out  = (float*)d_out;
    float* act  = out;                                   // [1024, 32768]
    float* bidx = out + (size_t)BATCH * NCONCEPT;        // [1024] as float

    float *pP = nullptr, *pS = nullptr;
    char *pFh = nullptr, *pFl = nullptr, *pWh = nullptr, *pWl = nullptr;
    char *pAh = nullptr, *pAl = nullptr, *pBh = nullptr;
    cudaGetSymbolAddress((void**)&pP,  g_P);
    cudaGetSymbolAddress((void**)&pS,  g_S);
    cudaGetSymbolAddress((void**)&pFh, g_Fh);
    cudaGetSymbolAddress((void**)&pFl, g_Fl);
    cudaGetSymbolAddress((void**)&pWh, g_Wh);
    cudaGetSymbolAddress((void**)&pWl, g_Wl);
    cudaGetSymbolAddress((void**)&pAh, g_Ah);
    cudaGetSymbolAddress((void**)&pAl, g_Al);
    cudaGetSymbolAddress((void**)&pBh, g_Bh);

    cudaFuncSetAttribute(proj_mma, cudaFuncAttributeMaxDynamicSharedMemorySize, SMEM_PROJ);
    cudaFuncSetAttribute(sim_mma,  cudaFuncAttributeMaxDynamicSharedMemorySize, SMEM_SIM);

    // 1) split features and W into fp16 limbs (pre-swizzled tiles)
    convert_split2<<<(BATCH * FDIM / 4) / 256, 256>>>((const float4*)features, pFh, pFl);
    convert_split2<<<(FDIM * FDIM / 4) / 256, 256>>>((const float4*)W, pWh, pWl);

    // 2) projection via fp16 3-term mma: P = F @ W^T + b
    proj_mma<<<dim3(BATCH / 128, FDIM / 128), 512, SMEM_PROJ>>>(
        pFh, pFl, pWh, pWl, b, pP);

    // 3) A: fused L2-normalize + fp16 two-limb split; B: fp16 hi limb
    convert_a<<<BATCH, 256>>>((const float4*)pP, pAh, pAl);
    convert_b<<<(NCONCEPT * FDIM / 4) / 256, 256>>>((const float4*)prototypes, pBh);

    // 4) similarities via fp16 two-term mma.sync
    sim_mma<<<dim3(BATCH / 128, NCONCEPT / 128), 512, SMEM_SIM>>>(
        pAh, pAl, pBh, pS);

    // 5) per-row softmax(S/T) + argmax
    softmax_row<<<BATCH, 256>>>(pS, act, bidx);
}

// round 7
// speedup vs baseline: 3.8900x; 1.0937x over previous
#include <cuda_runtime.h>
#include <cuda_fp16.h>
#include <math.h>
#include <stdint.h>

// Problem constants
#define BATCH     1024
#define FDIM      1024
#define NCONCEPT  32768
#define INV_T     10.0f   // 1 / 0.1

#define TILE_B    16384          // one 128x64-fp16 swizzled tile (128 rows * 128 B)
#define KCHUNKS   16             // 1024 / 64
#define LO_SCALE  2048.0f        // 2^11: keeps lo limbs in fp16 normal range

// sim pipeline: Ahi, Bhi per stage = 32 KB, 3 stages, 2 CTAs/SM
#define STAGE_S   (2 * TILE_B)
#define NSTAGES_S 3
#define SMEM_SIM  (1024 + NSTAGES_S * STAGE_S)
// proj pipeline: Fhi, Flo, Whi, Wlo per stage = 64 KB, 3 stages
#define STAGE_P   (4 * TILE_B)
#define NSTAGES_P 3
#define SMEM_PROJ (1024 + NSTAGES_P * STAGE_P)

// ---------------- scratch (device globals; no allocation allowed) ----------
__device__ float g_P[BATCH * FDIM];                      // projection output
__device__ float g_S[(size_t)BATCH * NCONCEPT];          // similarities (134 MB)
__device__ __align__(256) char g_Fh[(size_t)BATCH * FDIM * 2];     // features limbs
__device__ __align__(256) char g_Fl[(size_t)BATCH * FDIM * 2];
__device__ __align__(256) char g_Wh[(size_t)FDIM * FDIM * 2];      // W limbs
__device__ __align__(256) char g_Wl[(size_t)FDIM * FDIM * 2];
__device__ __align__(256) char g_Ah[(size_t)BATCH * FDIM * 2];     // normalized P hi limb
__device__ __align__(256) char g_Bh[(size_t)NCONCEPT * FDIM * 2];  // prototypes hi limb

// ---------------------------------------------------------------------------
// PTX helpers (baseline ISA only)
// ---------------------------------------------------------------------------
__device__ __forceinline__ uint32_t sm_u32(const void* p) {
    uint32_t a;
    asm("{ .reg .u64 t; cvta.to.shared.u64 t, %1; cvt.u32.u64 %0, t; }"
        : "=r"(a) : "l"(p));
    return a;
}

__device__ __forceinline__ void mbar_wait(uint32_t addr, int phase) {
    asm volatile(
        "{\n\t.reg .pred P;\n\t"
        "WL_%=:\n\t"
        "mbarrier.try_wait.parity.acquire.cta.shared::cta.b64 P, [%0], %1, 0x989680;\n\t"
        "@P bra.uni WD_%=;\n\t"
        "bra.uni WL_%=;\n\t"
        "WD_%=:\n\t}"
        :: "r"(addr), "r"((uint32_t)phase) : "memory");
}

#define LDSM4(R, addr) \
    asm volatile("ldmatrix.sync.aligned.m8n8.x4.shared.b16 {%0,%1,%2,%3}, [%4];" \
        : "=r"((R)[0]), "=r"((R)[1]), "=r"((R)[2]), "=r"((R)[3]) : "r"(addr))

#define MMA_F16_F32(C, A, b0_, b1_) \
    asm volatile("mma.sync.aligned.m16n8k16.row.col.f32.f16.f16.f32 " \
        "{%0,%1,%2,%3}, {%4,%5,%6,%7}, {%8,%9}, {%0,%1,%2,%3};" \
        : "+f"((C)[0]), "+f"((C)[1]), "+f"((C)[2]), "+f"((C)[3]) \
        : "r"((A)[0]), "r"((A)[1]), "r"((A)[2]), "r"((A)[3]), "r"(b0_), "r"(b1_))

#define MMA_F16_F16(C, A, b0_, b1_) \
    asm volatile("mma.sync.aligned.m16n8k16.row.col.f16.f16.f16.f16 " \
        "{%0,%1}, {%2,%3,%4,%5}, {%6,%7}, {%0,%1};" \
        : "+r"((C)[0]), "+r"((C)[1]) \
        : "r"((A)[0]), "r"((A)[1]), "r"((A)[2]), "r"((A)[3]), "r"(b0_), "r"(b1_))

#define BULK_LOAD(dst, src, bar) \
    asm volatile("cp.async.bulk.shared::cluster.global.mbarrier::complete_tx::bytes " \
        "[%0], [%1], %2, [%3];" \
        :: "r"(dst), "l"(src), "r"((uint32_t)TILE_B), "r"(bar) : "memory")

// ---------------------------------------------------------------------------
// fp32 -> fp16 two-limb split into pre-swizzled 128x64 tiles (no norm).
// ---------------------------------------------------------------------------
__global__ void __launch_bounds__(256)
convert_split2(const float4* __restrict__ src, char* __restrict__ hi, char* __restrict__ lo)
{
    const size_t i4 = (size_t)blockIdx.x * 256 + threadIdx.x;
    const int row = (int)(i4 >> 8);
    const int k   = ((int)i4 & 255) * 4;
    const float4 v = src[i4];
    const float x[4] = {v.x, v.y, v.z, v.w};

    unsigned short h[4], l[4];
#pragma unroll
    for (int j = 0; j < 4; ++j) {
        const __half hb = __float2half_rn(x[j]);
        const float r = (x[j] - __half2float(hb)) * LO_SCALE;
        h[j] = __half_as_ushort(hb);
        l[j] = __half_as_ushort(__float2half_rn(r));
    }

    const int tile = (row >> 7) * KCHUNKS + (k >> 6);
    uint32_t off = (uint32_t)((row & 127) * 128 + (k & 63) * 2);
    off ^= (off >> 3) & 0x70;

    uint2 ph, pl;
    ph.x = (uint32_t)h[0] | ((uint32_t)h[1] << 16);
    ph.y = (uint32_t)h[2] | ((uint32_t)h[3] << 16);
    pl.x = (uint32_t)l[0] | ((uint32_t)l[1] << 16);
    pl.y = (uint32_t)l[2] | ((uint32_t)l[3] << 16);
    *(uint2*)(hi + (size_t)tile * TILE_B + off) = ph;
    *(uint2*)(lo + (size_t)tile * TILE_B + off) = pl;
}

// ---------------------------------------------------------------------------
// A-side: fused L2-normalize + fp16 hi limb only. One CTA per row.
// ---------------------------------------------------------------------------
__global__ void __launch_bounds__(256)
convert_a(const float4* __restrict__ src, char* __restrict__ hi)
{
    const int row = blockIdx.x;
    const int tid = threadIdx.x;
    const float4 v = src[(size_t)row * 256 + tid];
    const float x[4] = {v.x, v.y, v.z, v.w};

    __shared__ float red[256];
    red[tid] = x[0]*x[0] + x[1]*x[1] + x[2]*x[2] + x[3]*x[3];
    __syncthreads();
#pragma unroll
    for (int off = 128; off > 0; off >>= 1) {
        if (tid < off) red[tid] += red[tid + off];
        __syncthreads();
    }
    const float inv = 1.0f / fmaxf(sqrtf(red[0]), 1e-12f);

    unsigned short h[4];
#pragma unroll
    for (int j = 0; j < 4; ++j)
        h[j] = __half_as_ushort(__float2half_rn(x[j] * inv));

    const int k = tid * 4;
    const int tile = (row >> 7) * KCHUNKS + (k >> 6);
    uint32_t off = (uint32_t)((row & 127) * 128 + (k & 63) * 2);
    off ^= (off >> 3) & 0x70;

    uint2 ph;
    ph.x = (uint32_t)h[0] | ((uint32_t)h[1] << 16);
    ph.y = (uint32_t)h[2] | ((uint32_t)h[3] << 16);
    *(uint2*)(hi + (size_t)tile * TILE_B + off) = ph;
}

// ---------------------------------------------------------------------------
// B-side: fp16 hi limb only, pre-swizzled tiles.
// ---------------------------------------------------------------------------
__global__ void __launch_bounds__(256)
convert_b(const float4* __restrict__ src, char* __restrict__ hi)
{
    const size_t i4 = (size_t)blockIdx.x * 256 + threadIdx.x;
    const int row = (int)(i4 >> 8);
    const int k   = ((int)i4 & 255) * 4;
    const float4 v = src[i4];
    const float x[4] = {v.x, v.y, v.z, v.w};

    unsigned short h[4];
#pragma unroll
    for (int j = 0; j < 4; ++j)
        h[j] = __half_as_ushort(__float2half_rn(x[j]));

    const int tile = (row >> 7) * KCHUNKS + (k >> 6);
    uint32_t off = (uint32_t)((row & 127) * 128 + (k & 63) * 2);
    off ^= (off >> 3) & 0x70;

    uint2 ph;
    ph.x = (uint32_t)h[0] | ((uint32_t)h[1] << 16);
    ph.y = (uint32_t)h[2] | ((uint32_t)h[3] << 16);
    *(uint2*)(hi + (size_t)tile * TILE_B + off) = ph;
}

// ---------------------------------------------------------------------------
// Projection GEMM, fp16 3-term limbs (~fp32):
//   P[m,n] = Fhi.Whi (f32) + (Fhi.Wlo + Flo.Whi) (f16) * 2^-11 + bias[n]
// CTA 128x128, 16 warps (4M x 4N, warp tile 32x32). 3-stage 64KB pipeline.
// ---------------------------------------------------------------------------
__global__ void __launch_bounds__(512, 1)
proj_mma(const char* __restrict__ Fh, const char* __restrict__ Fl,
         const char* __restrict__ Wh, const char* __restrict__ Wl,
         const float* __restrict__ bias, float* __restrict__ P)
{
    extern __shared__ char smem_raw[];
    const uint32_t sbase = sm_u32(smem_raw);
    const uint32_t mbar0 = sbase;
    const uint32_t data0 = (sbase + 32u + 1023u) & ~1023u;

    const int tid = threadIdx.x;
    const int w = tid >> 5, l = tid & 31;
    const int wm = w & 3;
    const int wn = w >> 2;        // 0..3
    const int mb = blockIdx.x;    // 0..7
    const int nb = blockIdx.y;    // 0..7

    if (tid == 0) {
#pragma unroll
        for (int s = 0; s < NSTAGES_P; ++s)
            asm volatile("mbarrier.init.shared.b64 [%0], 1;" :: "r"(mbar0 + s * 8) : "memory");
    }
    __syncthreads();

    const int rowA  = wm * 32 + (l & 15);
    const uint32_t hA = (uint32_t)(l >> 4) << 4;
    const int rowB0 = wn * 32 + (l & 7) + ((l & 16) >> 1);
    const uint32_t hB = (uint32_t)(l & 8) << 1;
    const uint32_t swz = (uint32_t)(l & 7) << 4;

    float    acc[2][4][4];
    uint32_t accC[2][4][2];
#pragma unroll
    for (int i = 0; i < 2; ++i)
#pragma unroll
        for (int j = 0; j < 4; ++j) {
#pragma unroll
            for (int q = 0; q < 4; ++q) acc[i][j][q] = 0.f;
            accC[i][j][0] = 0u; accC[i][j][1] = 0u;
        }

    auto issue = [&](int kc, int s) {
        const uint32_t d = data0 + s * STAGE_P;
        const uint32_t bar = mbar0 + s * 8;
        const size_t aoff = ((size_t)mb * KCHUNKS + kc) * TILE_B;
        const size_t boff = ((size_t)nb * KCHUNKS + kc) * TILE_B;
        asm volatile("mbarrier.arrive.expect_tx.shared.b64 _, [%0], %1;"
                     :: "r"(bar), "r"((uint32_t)STAGE_P) : "memory");
        BULK_LOAD(d,              Fh + aoff, bar);
        BULK_LOAD(d + 1 * TILE_B, Fl + aoff, bar);
        BULK_LOAD(d + 2 * TILE_B, Wh + boff, bar);
        BULK_LOAD(d + 3 * TILE_B, Wl + boff, bar);
    };

    if (tid == 0) { issue(0, 0); issue(1, 1); }

    int ph[NSTAGES_P] = {0, 0, 0};

    for (int kc = 0; kc < KCHUNKS; ++kc) {
        const int s = kc % NSTAGES_P;
        mbar_wait(mbar0 + s * 8, ph[s]);
        ph[s] ^= 1;
        __syncthreads();
        if (tid == 0 && kc + 2 < KCHUNKS) issue(kc + 2, (kc + 2) % NSTAGES_P);

        const uint32_t aHb = data0 + s * STAGE_P;
        const uint32_t aLb = aHb + 1 * TILE_B;
        const uint32_t bHb = aHb + 2 * TILE_B;
        const uint32_t bLb = aHb + 3 * TILE_B;

#pragma unroll
        for (int ks = 0; ks < 4; ++ks) {
            uint32_t ah[2][4], al[2][4];
#pragma unroll
            for (int mi = 0; mi < 2; ++mi) {
                const uint32_t pa =
                    ((uint32_t)((rowA + mi * 16) * 128) + (uint32_t)(ks * 32) + hA) ^ swz;
                LDSM4(ah[mi], aHb + pa);
                LDSM4(al[mi], aLb + pa);
            }
#pragma unroll
            for (int nk = 0; nk < 2; ++nk) {
                const uint32_t pb =
                    ((uint32_t)((rowB0 + nk * 16) * 128) + (uint32_t)(ks * 32) + hB) ^ swz;
                uint32_t bh[4], bl[4];
                LDSM4(bh, bHb + pb);
                LDSM4(bl, bLb + pb);
#pragma unroll
                for (int mi = 0; mi < 2; ++mi) {
                    MMA_F16_F32(acc[mi][nk * 2 + 0], ah[mi], bh[0], bh[1]);
                    MMA_F16_F32(acc[mi][nk * 2 + 1], ah[mi], bh[2], bh[3]);
                    MMA_F16_F16(accC[mi][nk * 2 + 0], ah[mi], bl[0], bl[1]);
                    MMA_F16_F16(accC[mi][nk * 2 + 1], ah[mi], bl[2], bl[3]);
                    MMA_F16_F16(accC[mi][nk * 2 + 0], al[mi], bh[0], bh[1]);
                    MMA_F16_F16(accC[mi][nk * 2 + 1], al[mi], bh[2], bh[3]);
                }
            }
        }
    }

    const float cs = 1.0f / LO_SCALE;
    const int gm0 = mb * 128 + wm * 32 + (l >> 2);
    const int gn0 = nb * 128 + wn * 32 + (l & 3) * 2;
#pragma unroll
    for (int mi = 0; mi < 2; ++mi) {
#pragma unroll
        for (int nk = 0; nk < 2; ++nk) {
#pragma unroll
            for (int hf = 0; hf < 2; ++hf) {
                const int n = gn0 + nk * 16 + hf * 8;
                const float b0 = bias[n], b1 = bias[n + 1];
                const float* a = acc[mi][nk * 2 + hf];
                const uint32_t* c = accC[mi][nk * 2 + hf];
                const __half2 c0 = *(const __half2*)&c[0];
                const __half2 c1 = *(const __half2*)&c[1];
                float* p = P + (size_t)(gm0 + mi * 16) * FDIM + n;
                float2 v0, v1;
                v0.x = a[0] + __half2float(__low2half(c0))  * cs + b0;
                v0.y = a[1] + __half2float(__high2half(c0)) * cs + b1;
                v1.x = a[2] + __half2float(__low2half(c1))  * cs + b0;
                v1.y = a[3] + __half2float(__high2half(c1)) * cs + b1;
                *(float2*)p = v0;
                *(float2*)(p + (size_t)8 * FDIM) = v1;
            }
        }
    }
}

// ---------------------------------------------------------------------------
// Similarity GEMM, single-term fp16 (Ahi.Bhi, fp32 accum).
// CTA 128x128, 16 warps (4M x 4N, warp tile 32x32). 3-stage 32KB pipeline,
// 2 CTAs per SM.
// ---------------------------------------------------------------------------
__global__ void __launch_bounds__(512, 2)
sim_mma(const char* __restrict__ Ah, const char* __restrict__ Bh,
        float* __restrict__ S)
{
    extern __shared__ char smem_raw[];
    const uint32_t sbase = sm_u32(smem_raw);
    const uint32_t mbar0 = sbase;
    const uint32_t data0 = (sbase + 32u + 1023u) & ~1023u;

    const int tid = threadIdx.x;
    const int w = tid >> 5, l = tid & 31;
    const int wm = w & 3;
    const int wn = w >> 2;        // 0..3
    const int mb = blockIdx.x;    // 0..7
    const int nb = blockIdx.y;    // 0..255

    if (tid == 0) {
#pragma unroll
        for (int s = 0; s < NSTAGES_S; ++s)
            asm volatile("mbarrier.init.shared.b64 [%0], 1;" :: "r"(mbar0 + s * 8) : "memory");
    }
    __syncthreads();

    const int rowA  = wm * 32 + (l & 15);
    const uint32_t hA = (uint32_t)(l >> 4) << 4;
    const int rowB0 = wn * 32 + (l & 7) + ((l & 16) >> 1);
    const uint32_t hB = (uint32_t)(l & 8) << 1;
    const uint32_t swz = (uint32_t)(l & 7) << 4;

    float acc[2][4][4];
#pragma unroll
    for (int i = 0; i < 2; ++i)
#pragma unroll
        for (int j = 0; j < 4; ++j)
#pragma unroll
            for (int q = 0; q < 4; ++q) acc[i][j][q] = 0.f;

    auto issue = [&](int kc, int s) {
        const uint32_t d = data0 + s * STAGE_S;
        const uint32_t bar = mbar0 + s * 8;
        const size_t aoff = ((size_t)mb * KCHUNKS + kc) * TILE_B;
        const size_t boff = ((size_t)nb * KCHUNKS + kc) * TILE_B;
        asm volatile("mbarrier.arrive.expect_tx.shared.b64 _, [%0], %1;"
                     :: "r"(bar), "r"((uint32_t)STAGE_S) : "memory");
        BULK_LOAD(d,          Ah + aoff, bar);
        BULK_LOAD(d + TILE_B, Bh + boff, bar);
    };

    if (tid == 0) { issue(0, 0); issue(1, 1); }

    int ph[NSTAGES_S] = {0, 0, 0};

    for (int kc = 0; kc < KCHUNKS; ++kc) {
        const int s = kc % NSTAGES_S;
        mbar_wait(mbar0 + s * 8, ph[s]);
        ph[s] ^= 1;
        __syncthreads();
        if (tid == 0 && kc + 2 < KCHUNKS) issue(kc + 2, (kc + 2) % NSTAGES_S);

        const uint32_t aHb = data0 + s * STAGE_S;
        const uint32_t bHb = aHb + TILE_B;

#pragma unroll
        for (int ks = 0; ks < 4; ++ks) {
            uint32_t ah[2][4];
#pragma unroll
            for (int mi = 0; mi < 2; ++mi) {
                const uint32_t pa =
                    ((uint32_t)((rowA + mi * 16) * 128) + (uint32_t)(ks * 32) + hA) ^ swz;
                LDSM4(ah[mi], aHb + pa);
            }
#pragma unroll
            for (int nk = 0; nk < 2; ++nk) {
                const uint32_t pb =
                    ((uint32_t)((rowB0 + nk * 16) * 128) + (uint32_t)(ks * 32) + hB) ^ swz;
                uint32_t bh[4];
                LDSM4(bh, bHb + pb);
#pragma unroll
                for (int mi = 0; mi < 2; ++mi) {
                    MMA_F16_F32(acc[mi][nk * 2 + 0], ah[mi], bh[0], bh[1]);
                    MMA_F16_F32(acc[mi][nk * 2 + 1], ah[mi], bh[2], bh[3]);
                }
            }
        }
    }

    const int gm0 = mb * 128 + wm * 32 + (l >> 2);
    const int gn0 = nb * 128 + wn * 32 + (l & 3) * 2;
#pragma unroll
    for (int mi = 0; mi < 2; ++mi) {
#pragma unroll
        for (int nk = 0; nk < 2; ++nk) {
#pragma unroll
            for (int hf = 0; hf < 2; ++hf) {
                const float* a = acc[mi][nk * 2 + hf];
                float* p = S + (size_t)(gm0 + mi * 16) * NCONCEPT + gn0 + nk * 16 + hf * 8;
                float2 v0, v1;
                v0.x = a[0]; v0.y = a[1];
                v1.x = a[2]; v1.y = a[3];
                *(float2*)p = v0;
                *(float2*)(p + (size_t)8 * NCONCEPT) = v1;
            }
        }
    }
}

// ---------------------------------------------------------------------------
// Per-row softmax(sim * INV_T) + argmax. One CTA (256 threads) per row.
// ---------------------------------------------------------------------------
__global__ void __launch_bounds__(256)
softmax_row(const float* __restrict__ S,
            float* __restrict__ act,
            float* __restrict__ bidx)
{
    const int row = blockIdx.x;
    const int tid = threadIdx.x;
    const float4* s4 = (const float4*)(S + (size_t)row * NCONCEPT);

    float m = -INFINITY;
    float Z = 0.f;
    int   bi = 0;

    for (int j = tid; j < NCONCEPT / 4; j += 256) {
        const float4 v = s4[j];
        const float x[4] = {v.x, v.y, v.z, v.w};
#pragma unroll
        for (int q = 0; q < 4; ++q) {
            if (x[q] > m) {
                Z = Z * __expf((m - x[q]) * INV_T) + 1.0f;
                m = x[q];
                bi = j * 4 + q;
            } else {
                Z += __expf((x[q] - m) * INV_T);
            }
        }
    }

    __shared__ float sm[256];
    __shared__ float sz[256];
    __shared__ int   si[256];
    sm[tid] = m; sz[tid] = Z; si[tid] = bi;
    __syncthreads();

#pragma unroll
    for (int off = 128; off > 0; off >>= 1) {
        if (tid < off) {
            const float m1 = sm[tid],       z1 = sz[tid];
            const float m2 = sm[tid + off], z2 = sz[tid + off];
            const int   i1 = si[tid],       i2 = si[tid + off];
            if (m2 > m1 || (m2 == m1 && i2 < i1)) {
                sm[tid] = m2;
                sz[tid] = z2 + z1 * __expf((m1 - m2) * INV_T);
                si[tid] = i2;
            } else {
                sz[tid] = z1 + z2 * __expf((m2 - m1) * INV_T);
            }
        }
        __syncthreads();
    }

    const float M    = sm[0];
    const float invZ = 1.0f / sz[0];
    float4* a4 = (float4*)(act + (size_t)row * NCONCEPT);
    for (int j = tid; j < NCONCEPT / 4; j += 256) {
        const float4 v = s4[j];
        float4 o;
        o.x = __expf((v.x - M) * INV_T) * invZ;
        o.y = __expf((v.y - M) * INV_T) * invZ;
        o.z = __expf((v.z - M) * INV_T) * invZ;
        o.w = __expf((v.w - M) * INV_T) * invZ;
        a4[j] = o;
    }

    if (tid == 0) bidx[row] = (float)si[0];
}

// ---------------------------------------------------------------------------
extern "C" void kernel_launch(void* const* d_in, const int* in_sizes, int n_in,
                              void* d_out, int out_size)
{
    const float* features   = (const float*)d_in[0];  // [1024, 1024]
    const float* W          = (const float*)d_in[1];  // [1024, 1024]
    const float* b          = (const float*)d_in[2];  // [1024]
    const float* prototypes = (const float*)d_in[3];  // [32768, 1024]

    float* out  = (float*)d_out;
    float* act  = out;                                   // [1024, 32768]
    float* bidx = out + (size_t)BATCH * NCONCEPT;        // [1024] as float

    float *pP = nullptr, *pS = nullptr;
    char *pFh = nullptr, *pFl = nullptr, *pWh = nullptr, *pWl = nullptr;
    char *pAh = nullptr, *pBh = nullptr;
    cudaGetSymbolAddress((void**)&pP,  g_P);
    cudaGetSymbolAddress((void**)&pS,  g_S);
    cudaGetSymbolAddress((void**)&pFh, g_Fh);
    cudaGetSymbolAddress((void**)&pFl, g_Fl);
    cudaGetSymbolAddress((void**)&pWh, g_Wh);
    cudaGetSymbolAddress((void**)&pWl, g_Wl);
    cudaGetSymbolAddress((void**)&pAh, g_Ah);
    cudaGetSymbolAddress((void**)&pBh, g_Bh);

    cudaFuncSetAttribute(proj_mma, cudaFuncAttributeMaxDynamicSharedMemorySize, SMEM_PROJ);
    cudaFuncSetAttribute(sim_mma,  cudaFuncAttributeMaxDynamicSharedMemorySize, SMEM_SIM);

    // 1) split features and W into fp16 limbs (pre-swizzled tiles)
    convert_split2<<<(BATCH * FDIM / 4) / 256, 256>>>((const float4*)features, pFh, pFl);
    convert_split2<<<(FDIM * FDIM / 4) / 256, 256>>>((const float4*)W, pWh, pWl);

    // 2) projection via fp16 3-term mma: P = F @ W^T + b
    proj_mma<<<dim3(BATCH / 128, FDIM / 128), 512, SMEM_PROJ>>>(
        pFh, pFl, pWh, pWl, b, pP);

    // 3) A: fused L2-normalize + fp16 hi limb; B: fp16 hi limb
    convert_a<<<BATCH, 256>>>((const float4*)pP, pAh);
    convert_b<<<(NCONCEPT * FDIM / 4) / 256, 256>>>((const float4*)prototypes, pBh);

    // 4) similarities via single-term fp16 mma.sync (f32 accum)
    sim_mma<<<dim3(BATCH / 128, NCONCEPT / 128), 512, SMEM_SIM>>>(pAh, pBh, pS);

    // 5) per-row softmax(S/T) + argmax
    softmax_row<<<BATCH, 256>>>(pS, act, bidx);
}

// round 8
// speedup vs baseline: 4.6840x; 1.2041x over previous
#include <cuda_runtime.h>
#include <cuda_fp16.h>
#include <math.h>
#include <stdint.h>

// Problem constants
#define BATCH     1024
#define FDIM      1024
#define NCONCEPT  32768
#define INV_T     10.0f   // 1 / 0.1

#define TILE_B    16384          // one 128x64-fp16 swizzled tile (128 rows * 128 B)
#define KCHUNKS   16             // 1024 / 64
#define LO_SCALE  2048.0f        // 2^11

// sim pipeline: A (1 tile) + B (2 tiles) per stage = 48 KB, 3 stages
#define STAGE_S   (3 * TILE_B)
#define NSTAGES_S 3
#define SMEM_SIM  (1024 + NSTAGES_S * STAGE_S)
// proj pipeline: Fhi, Flo, Whi, Wlo per stage = 64 KB, 3 stages
#define STAGE_P   (4 * TILE_B)
#define NSTAGES_P 3
#define SMEM_PROJ (1024 + NSTAGES_P * STAGE_P)
// softmax: full row staged in smem
#define SMEM_SOFT (NCONCEPT * 4)

// ---------------- scratch (device globals; no allocation allowed) ----------
__device__ float g_P[BATCH * FDIM];
__device__ float g_S[(size_t)BATCH * NCONCEPT];          // similarities (134 MB)
__device__ __align__(256) char g_Fh[(size_t)BATCH * FDIM * 2];
__device__ __align__(256) char g_Fl[(size_t)BATCH * FDIM * 2];
__device__ __align__(256) char g_Wh[(size_t)FDIM * FDIM * 2];
__device__ __align__(256) char g_Wl[(size_t)FDIM * FDIM * 2];
__device__ __align__(256) char g_Ah[(size_t)BATCH * FDIM * 2];
__device__ __align__(256) char g_Bh[(size_t)NCONCEPT * FDIM * 2];

// ---------------------------------------------------------------------------
// PTX helpers (baseline ISA only)
// ---------------------------------------------------------------------------
__device__ __forceinline__ uint32_t sm_u32(const void* p) {
    uint32_t a;
    asm("{ .reg .u64 t; cvta.to.shared.u64 t, %1; cvt.u32.u64 %0, t; }"
        : "=r"(a) : "l"(p));
    return a;
}

__device__ __forceinline__ void mbar_wait(uint32_t addr, int phase) {
    asm volatile(
        "{\n\t.reg .pred P;\n\t"
        "WL_%=:\n\t"
        "mbarrier.try_wait.parity.acquire.cta.shared::cta.b64 P, [%0], %1, 0x989680;\n\t"
        "@P bra.uni WD_%=;\n\t"
        "bra.uni WL_%=;\n\t"
        "WD_%=:\n\t}"
        :: "r"(addr), "r"((uint32_t)phase) : "memory");
}

#define LDSM4(R, addr) \
    asm volatile("ldmatrix.sync.aligned.m8n8.x4.shared.b16 {%0,%1,%2,%3}, [%4];" \
        : "=r"((R)[0]), "=r"((R)[1]), "=r"((R)[2]), "=r"((R)[3]) : "r"(addr))

#define MMA_F16_F32(C, A, b0_, b1_) \
    asm volatile("mma.sync.aligned.m16n8k16.row.col.f32.f16.f16.f32 " \
        "{%0,%1,%2,%3}, {%4,%5,%6,%7}, {%8,%9}, {%0,%1,%2,%3};" \
        : "+f"((C)[0]), "+f"((C)[1]), "+f"((C)[2]), "+f"((C)[3]) \
        : "r"((A)[0]), "r"((A)[1]), "r"((A)[2]), "r"((A)[3]), "r"(b0_), "r"(b1_))

#define MMA_F16_F16(C, A, b0_, b1_) \
    asm volatile("mma.sync.aligned.m16n8k16.row.col.f16.f16.f16.f16 " \
        "{%0,%1}, {%2,%3,%4,%5}, {%6,%7}, {%0,%1};" \
        : "+r"((C)[0]), "+r"((C)[1]) \
        : "r"((A)[0]), "r"((A)[1]), "r"((A)[2]), "r"((A)[3]), "r"(b0_), "r"(b1_))

#define BULK_LOAD(dst, src, bar) \
    asm volatile("cp.async.bulk.shared::cluster.global.mbarrier::complete_tx::bytes " \
        "[%0], [%1], %2, [%3];" \
        :: "r"(dst), "l"(src), "r"((uint32_t)TILE_B), "r"(bar) : "memory")

// ---------------------------------------------------------------------------
// fp32 -> fp16 two-limb split into pre-swizzled 128x64 tiles (no norm).
// ---------------------------------------------------------------------------
__global__ void __launch_bounds__(256)
convert_split2(const float4* __restrict__ src, char* __restrict__ hi, char* __restrict__ lo)
{
    const size_t i4 = (size_t)blockIdx.x * 256 + threadIdx.x;
    const int row = (int)(i4 >> 8);
    const int k   = ((int)i4 & 255) * 4;
    const float4 v = src[i4];
    const float x[4] = {v.x, v.y, v.z, v.w};

    unsigned short h[4], l[4];
#pragma unroll
    for (int j = 0; j < 4; ++j) {
        const __half hb = __float2half_rn(x[j]);
        const float r = (x[j] - __half2float(hb)) * LO_SCALE;
        h[j] = __half_as_ushort(hb);
        l[j] = __half_as_ushort(__float2half_rn(r));
    }

    const int tile = (row >> 7) * KCHUNKS + (k >> 6);
    uint32_t off = (uint32_t)((row & 127) * 128 + (k & 63) * 2);
    off ^= (off >> 3) & 0x70;

    uint2 ph, pl;
    ph.x = (uint32_t)h[0] | ((uint32_t)h[1] << 16);
    ph.y = (uint32_t)h[2] | ((uint32_t)h[3] << 16);
    pl.x = (uint32_t)l[0] | ((uint32_t)l[1] << 16);
    pl.y = (uint32_t)l[2] | ((uint32_t)l[3] << 16);
    *(uint2*)(hi + (size_t)tile * TILE_B + off) = ph;
    *(uint2*)(lo + (size_t)tile * TILE_B + off) = pl;
}

// ---------------------------------------------------------------------------
// A-side: fused L2-normalize + fp16 hi limb only. One CTA per row.
// ---------------------------------------------------------------------------
__global__ void __launch_bounds__(256)
convert_a(const float4* __restrict__ src, char* __restrict__ hi)
{
    const int row = blockIdx.x;
    const int tid = threadIdx.x;
    const float4 v = src[(size_t)row * 256 + tid];
    const float x[4] = {v.x, v.y, v.z, v.w};

    __shared__ float red[256];
    red[tid] = x[0]*x[0] + x[1]*x[1] + x[2]*x[2] + x[3]*x[3];
    __syncthreads();
#pragma unroll
    for (int off = 128; off > 0; off >>= 1) {
        if (tid < off) red[tid] += red[tid + off];
        __syncthreads();
    }
    const float inv = 1.0f / fmaxf(sqrtf(red[0]), 1e-12f);

    unsigned short h[4];
#pragma unroll
    for (int j = 0; j < 4; ++j)
        h[j] = __half_as_ushort(__float2half_rn(x[j] * inv));

    const int k = tid * 4;
    const int tile = (row >> 7) * KCHUNKS + (k >> 6);
    uint32_t off = (uint32_t)((row & 127) * 128 + (k & 63) * 2);
    off ^= (off >> 3) & 0x70;

    uint2 ph;
    ph.x = (uint32_t)h[0] | ((uint32_t)h[1] << 16);
    ph.y = (uint32_t)h[2] | ((uint32_t)h[3] << 16);
    *(uint2*)(hi + (size_t)tile * TILE_B + off) = ph;
}

// ---------------------------------------------------------------------------
// B-side: fp16 hi limb only, pre-swizzled tiles.
// ---------------------------------------------------------------------------
__global__ void __launch_bounds__(256)
convert_b(const float4* __restrict__ src, char* __restrict__ hi)
{
    const size_t i4 = (size_t)blockIdx.x * 256 + threadIdx.x;
    const int row = (int)(i4 >> 8);
    const int k   = ((int)i4 & 255) * 4;
    const float4 v = src[i4];
    const float x[4] = {v.x, v.y, v.z, v.w};

    unsigned short h[4];
#pragma unroll
    for (int j = 0; j < 4; ++j)
        h[j] = __half_as_ushort(__float2half_rn(x[j]));

    const int tile = (row >> 7) * KCHUNKS + (k >> 6);
    uint32_t off = (uint32_t)((row & 127) * 128 + (k & 63) * 2);
    off ^= (off >> 3) & 0x70;

    uint2 ph;
    ph.x = (uint32_t)h[0] | ((uint32_t)h[1] << 16);
    ph.y = (uint32_t)h[2] | ((uint32_t)h[3] << 16);
    *(uint2*)(hi + (size_t)tile * TILE_B + off) = ph;
}

// ---------------------------------------------------------------------------
// Projection GEMM, fp16 3-term limbs (~fp32):
//   P[m,n] = Fhi.Whi (f32) + (Fhi.Wlo + Flo.Whi) (f16) * 2^-11 + bias[n]
// CTA 128x128, 16 warps (4M x 4N, warp tile 32x32). 3-stage 64KB pipeline.
// ---------------------------------------------------------------------------
__global__ void __launch_bounds__(512, 1)
proj_mma(const char* __restrict__ Fh, const char* __restrict__ Fl,
         const char* __restrict__ Wh, const char* __restrict__ Wl,
         const float* __restrict__ bias, float* __restrict__ P)
{
    extern __shared__ char smem_raw[];
    const uint32_t sbase = sm_u32(smem_raw);
    const uint32_t mbar0 = sbase;
    const uint32_t data0 = (sbase + 32u + 1023u) & ~1023u;

    const int tid = threadIdx.x;
    const int w = tid >> 5, l = tid & 31;
    const int wm = w & 3;
    const int wn = w >> 2;
    const int mb = blockIdx.x;
    const int nb = blockIdx.y;

    if (tid == 0) {
#pragma unroll
        for (int s = 0; s < NSTAGES_P; ++s)
            asm volatile("mbarrier.init.shared.b64 [%0], 1;" :: "r"(mbar0 + s * 8) : "memory");
    }
    __syncthreads();

    const int rowA  = wm * 32 + (l & 15);
    const uint32_t hA = (uint32_t)(l >> 4) << 4;
    const int rowB0 = wn * 32 + (l & 7) + ((l & 16) >> 1);
    const uint32_t hB = (uint32_t)(l & 8) << 1;
    const uint32_t swz = (uint32_t)(l & 7) << 4;

    float    acc[2][4][4];
    uint32_t accC[2][4][2];
#pragma unroll
    for (int i = 0; i < 2; ++i)
#pragma unroll
        for (int j = 0; j < 4; ++j) {
#pragma unroll
            for (int q = 0; q < 4; ++q) acc[i][j][q] = 0.f;
            accC[i][j][0] = 0u; accC[i][j][1] = 0u;
        }

    auto issue = [&](int kc, int s) {
        const uint32_t d = data0 + s * STAGE_P;
        const uint32_t bar = mbar0 + s * 8;
        const size_t aoff = ((size_t)mb * KCHUNKS + kc) * TILE_B;
        const size_t boff = ((size_t)nb * KCHUNKS + kc) * TILE_B;
        asm volatile("mbarrier.arrive.expect_tx.shared.b64 _, [%0], %1;"
                     :: "r"(bar), "r"((uint32_t)STAGE_P) : "memory");
        BULK_LOAD(d,              Fh + aoff, bar);
        BULK_LOAD(d + 1 * TILE_B, Fl + aoff, bar);
        BULK_LOAD(d + 2 * TILE_B, Wh + boff, bar);
        BULK_LOAD(d + 3 * TILE_B, Wl + boff, bar);
    };

    if (tid == 0) { issue(0, 0); issue(1, 1); }

    int ph[NSTAGES_P] = {0, 0, 0};

    for (int kc = 0; kc < KCHUNKS; ++kc) {
        const int s = kc % NSTAGES_P;
        mbar_wait(mbar0 + s * 8, ph[s]);
        ph[s] ^= 1;
        __syncthreads();
        if (tid == 0 && kc + 2 < KCHUNKS) issue(kc + 2, (kc + 2) % NSTAGES_P);

        const uint32_t aHb = data0 + s * STAGE_P;
        const uint32_t aLb = aHb + 1 * TILE_B;
        const uint32_t bHb = aHb + 2 * TILE_B;
        const uint32_t bLb = aHb + 3 * TILE_B;

#pragma unroll
        for (int ks = 0; ks < 4; ++ks) {
            uint32_t ah[2][4], al[2][4];
#pragma unroll
            for (int mi = 0; mi < 2; ++mi) {
                const uint32_t pa =
                    ((uint32_t)((rowA + mi * 16) * 128) + (uint32_t)(ks * 32) + hA) ^ swz;
                LDSM4(ah[mi], aHb + pa);
                LDSM4(al[mi], aLb + pa);
            }
#pragma unroll
            for (int nk = 0; nk < 2; ++nk) {
                const uint32_t pb =
                    ((uint32_t)((rowB0 + nk * 16) * 128) + (uint32_t)(ks * 32) + hB) ^ swz;
                uint32_t bh[4], bl[4];
                LDSM4(bh, bHb + pb);
                LDSM4(bl, bLb + pb);
#pragma unroll
                for (int mi = 0; mi < 2; ++mi) {
                    MMA_F16_F32(acc[mi][nk * 2 + 0], ah[mi], bh[0], bh[1]);
                    MMA_F16_F32(acc[mi][nk * 2 + 1], ah[mi], bh[2], bh[3]);
                    MMA_F16_F16(accC[mi][nk * 2 + 0], ah[mi], bl[0], bl[1]);
                    MMA_F16_F16(accC[mi][nk * 2 + 1], ah[mi], bl[2], bl[3]);
                    MMA_F16_F16(accC[mi][nk * 2 + 0], al[mi], bh[0], bh[1]);
                    MMA_F16_F16(accC[mi][nk * 2 + 1], al[mi], bh[2], bh[3]);
                }
            }
        }
    }

    const float cs = 1.0f / LO_SCALE;
    const int gm0 = mb * 128 + wm * 32 + (l >> 2);
    const int gn0 = nb * 128 + wn * 32 + (l & 3) * 2;
#pragma unroll
    for (int mi = 0; mi < 2; ++mi) {
#pragma unroll
        for (int nk = 0; nk < 2; ++nk) {
#pragma unroll
            for (int hf = 0; hf < 2; ++hf) {
                const int n = gn0 + nk * 16 + hf * 8;
                const float b0 = bias[n], b1 = bias[n + 1];
                const float* a = acc[mi][nk * 2 + hf];
                const uint32_t* c = accC[mi][nk * 2 + hf];
                const __half2 c0 = *(const __half2*)&c[0];
                const __half2 c1 = *(const __half2*)&c[1];
                float* p = P + (size_t)(gm0 + mi * 16) * FDIM + n;
                float2 v0, v1;
                v0.x = a[0] + __half2float(__low2half(c0))  * cs + b0;
                v0.y = a[1] + __half2float(__high2half(c0)) * cs + b1;
                v1.x = a[2] + __half2float(__low2half(c1))  * cs + b0;
                v1.y = a[3] + __half2float(__high2half(c1)) * cs + b1;
                *(float2*)p = v0;
                *(float2*)(p + (size_t)8 * FDIM) = v1;
            }
        }
    }
}

// ---------------------------------------------------------------------------
// Similarity GEMM, single-term fp16 (f32 accum).
// CTA tile 128x256: 16 warps, 4M x 4N, warp tile 32x64.
// Stage = A tile (16KB) + 2 B tiles (32KB) = 48KB; 3 stages.
// ---------------------------------------------------------------------------
__global__ void __launch_bounds__(512, 1)
sim_mma(const char* __restrict__ Ah, const char* __restrict__ Bh,
        float* __restrict__ S)
{
    extern __shared__ char smem_raw[];
    const uint32_t sbase = sm_u32(smem_raw);
    const uint32_t mbar0 = sbase;
    const uint32_t data0 = (sbase + 32u + 1023u) & ~1023u;

    const int tid = threadIdx.x;
    const int w = tid >> 5, l = tid & 31;
    const int wm = w & 3;         // M block of 32
    const int wn = w >> 2;        // 0..3, N block of 64
    const int mb = blockIdx.x;    // 0..7
    const int nb = blockIdx.y;    // 0..127  (256-wide N blocks)

    if (tid == 0) {
#pragma unroll
        for (int s = 0; s < NSTAGES_S; ++s)
            asm volatile("mbarrier.init.shared.b64 [%0], 1;" :: "r"(mbar0 + s * 8) : "memory");
    }
    __syncthreads();

    const int rowA  = wm * 32 + (l & 15);
    const uint32_t hA = (uint32_t)(l >> 4) << 4;
    // B: warp wn covers global cols nb*256 + wn*64 .. +63.
    // Tiles: wn 0,1 -> B tile (nb*2), wn 2,3 -> B tile (nb*2+1).
    const int rowB0 = (wn & 1) * 64 + (l & 7) + ((l & 16) >> 1);
    const uint32_t hB = (uint32_t)(l & 8) << 1;
    const uint32_t swz = (uint32_t)(l & 7) << 4;
    const uint32_t bsel = (uint32_t)(wn >> 1) * TILE_B;

    float acc[2][8][4];
#pragma unroll
    for (int i = 0; i < 2; ++i)
#pragma unroll
        for (int j = 0; j < 8; ++j)
#pragma unroll
            for (int q = 0; q < 4; ++q) acc[i][j][q] = 0.f;

    auto issue = [&](int kc, int s) {
        const uint32_t d = data0 + s * STAGE_S;
        const uint32_t bar = mbar0 + s * 8;
        const size_t aoff  = ((size_t)mb * KCHUNKS + kc) * TILE_B;
        const size_t boff0 = ((size_t)(nb * 2 + 0) * KCHUNKS + kc) * TILE_B;
        const size_t boff1 = ((size_t)(nb * 2 + 1) * KCHUNKS + kc) * TILE_B;
        asm volatile("mbarrier.arrive.expect_tx.shared.b64 _, [%0], %1;"
                     :: "r"(bar), "r"((uint32_t)STAGE_S) : "memory");
        BULK_LOAD(d,              Ah + aoff,  bar);
        BULK_LOAD(d + 1 * TILE_B, Bh + boff0, bar);
        BULK_LOAD(d + 2 * TILE_B, Bh + boff1, bar);
    };

    if (tid == 0) { issue(0, 0); issue(1, 1); }

    int ph[NSTAGES_S] = {0, 0, 0};

    for (int kc = 0; kc < KCHUNKS; ++kc) {
        const int s = kc % NSTAGES_S;
        mbar_wait(mbar0 + s * 8, ph[s]);
        ph[s] ^= 1;
        __syncthreads();
        if (tid == 0 && kc + 2 < KCHUNKS) issue(kc + 2, (kc + 2) % NSTAGES_S);

        const uint32_t aHb = data0 + s * STAGE_S;
        const uint32_t bHb = aHb + TILE_B + bsel;

#pragma unroll
        for (int ks = 0; ks < 4; ++ks) {
            uint32_t ah[2][4];
#pragma unroll
            for (int mi = 0; mi < 2; ++mi) {
                const uint32_t pa =
                    ((uint32_t)((rowA + mi * 16) * 128) + (uint32_t)(ks * 32) + hA) ^ swz;
                LDSM4(ah[mi], aHb + pa);
            }
#pragma unroll
            for (int nk = 0; nk < 4; ++nk) {
                const uint32_t pb =
                    ((uint32_t)((rowB0 + nk * 16) * 128) + (uint32_t)(ks * 32) + hB) ^ swz;
                uint32_t bh[4];
                LDSM4(bh, bHb + pb);
#pragma unroll
                for (int mi = 0; mi < 2; ++mi) {
                    MMA_F16_F32(acc[mi][nk * 2 + 0], ah[mi], bh[0], bh[1]);
                    MMA_F16_F32(acc[mi][nk * 2 + 1], ah[mi], bh[2], bh[3]);
                }
            }
        }
    }

    const int gm0 = mb * 128 + wm * 32 + (l >> 2);
    const int gn0 = nb * 256 + wn * 64 + (l & 3) * 2;
#pragma unroll
    for (int mi = 0; mi < 2; ++mi) {
#pragma unroll
        for (int nk = 0; nk < 4; ++nk) {
#pragma unroll
            for (int hf = 0; hf < 2; ++hf) {
                const float* a = acc[mi][nk * 2 + hf];
                float* p = S + (size_t)(gm0 + mi * 16) * NCONCEPT + gn0 + nk * 16 + hf * 8;
                float2 v0, v1;
                v0.x = a[0]; v0.y = a[1];
                v1.x = a[2]; v1.y = a[3];
                *(float2*)p = v0;
                *(float2*)(p + (size_t)8 * NCONCEPT) = v1;
            }
        }
    }
}

// ---------------------------------------------------------------------------
// Per-row softmax(sim * INV_T) + argmax, with the row staged in SMEM so
// global S is read once. One CTA (512 threads) per row; 128 KB dynamic smem.
// ---------------------------------------------------------------------------
__global__ void __launch_bounds__(512)
softmax_row(const float* __restrict__ S,
            float* __restrict__ act,
            float* __restrict__ bidx)
{
    extern __shared__ float srow[];          // 32768 floats
    const int row = blockIdx.x;
    const int tid = threadIdx.x;
    const float4* s4 = (const float4*)(S + (size_t)row * NCONCEPT);
    float4* r4 = (float4*)srow;

    float m = -INFINITY;
    float Z = 0.f;
    int   bi = 0;

    for (int j = tid; j < NCONCEPT / 4; j += 512) {
        const float4 v = s4[j];
        r4[j] = v;
        const float x[4] = {v.x, v.y, v.z, v.w};
#pragma unroll
        for (int q = 0; q < 4; ++q) {
            if (x[q] > m) {
                Z = Z * __expf((m - x[q]) * INV_T) + 1.0f;
                m = x[q];
                bi = j * 4 + q;
            } else {
                Z += __expf((x[q] - m) * INV_T);
            }
        }
    }

    __shared__ float sm[512];
    __shared__ float sz[512];
    __shared__ int   si[512];
    sm[tid] = m; sz[tid] = Z; si[tid] = bi;
    __syncthreads();

#pragma unroll
    for (int off = 256; off > 0; off >>= 1) {
        if (tid < off) {
            const float m1 = sm[tid],       z1 = sz[tid];
            const float m2 = sm[tid + off], z2 = sz[tid + off];
            const int   i1 = si[tid],       i2 = si[tid + off];
            if (m2 > m1 || (m2 == m1 && i2 < i1)) {
                sm[tid] = m2;
                sz[tid] = z2 + z1 * __expf((m1 - m2) * INV_T);
                si[tid] = i2;
            } else {
                sz[tid] = z1 + z2 * __expf((m2 - m1) * INV_T);
            }
        }
        __syncthreads();
    }

    const float M    = sm[0];
    const float invZ = 1.0f / sz[0];
    float4* a4 = (float4*)(act + (size_t)row * NCONCEPT);
    for (int j = tid; j < NCONCEPT / 4; j += 512) {
        const float4 v = r4[j];
        float4 o;
        o.x = __expf((v.x - M) * INV_T) * invZ;
        o.y = __expf((v.y - M) * INV_T) * invZ;
        o.z = __expf((v.z - M) * INV_T) * invZ;
        o.w = __expf((v.w - M) * INV_T) * invZ;
        a4[j] = o;
    }

    if (tid == 0) bidx[row] = (float)si[0];
}

// ---------------------------------------------------------------------------
extern "C" void kernel_launch(void* const* d_in, const int* in_sizes, int n_in,
                              void* d_out, int out_size)
{
    const float* features   = (const float*)d_in[0];  // [1024, 1024]
    const float* W          = (const float*)d_in[1];  // [1024, 1024]
    const float* b          = (const float*)d_in[2];  // [1024]
    const float* prototypes = (const float*)d_in[3];  // [32768, 1024]

    float* out  = (float*)d_out;
    float* act  = out;                                   // [1024, 32768]
    float* bidx = out + (size_t)BATCH * NCONCEPT;        // [1024] as float

    float *pP = nullptr, *pS = nullptr;
    char *pFh = nullptr, *pFl = nullptr, *pWh = nullptr, *pWl = nullptr;
    char *pAh = nullptr, *pBh = nullptr;
    cudaGetSymbolAddress((void**)&pP,  g_P);
    cudaGetSymbolAddress((void**)&pS,  g_S);
    cudaGetSymbolAddress((void**)&pFh, g_Fh);
    cudaGetSymbolAddress((void**)&pFl, g_Fl);
    cudaGetSymbolAddress((void**)&pWh, g_Wh);
    cudaGetSymbolAddress((void**)&pWl, g_Wl);
    cudaGetSymbolAddress((void**)&pAh, g_Ah);
    cudaGetSymbolAddress((void**)&pBh, g_Bh);

    cudaFuncSetAttribute(proj_mma, cudaFuncAttributeMaxDynamicSharedMemorySize, SMEM_PROJ);
    cudaFuncSetAttribute(sim_mma,  cudaFuncAttributeMaxDynamicSharedMemorySize, SMEM_SIM);
    cudaFuncSetAttribute(softmax_row, cudaFuncAttributeMaxDynamicSharedMemorySize, SMEM_SOFT);

    // 1) split features and W into fp16 limbs (pre-swizzled tiles)
    convert_split2<<<(BATCH * FDIM / 4) / 256, 256>>>((const float4*)features, pFh, pFl);
    convert_split2<<<(FDIM * FDIM / 4) / 256, 256>>>((const float4*)W, pWh, pWl);

    // 2) projection via fp16 3-term mma: P = F @ W^T + b
    proj_mma<<<dim3(BATCH / 128, FDIM / 128), 512, SMEM_PROJ>>>(
        pFh, pFl, pWh, pWl, b, pP);

    // 3) A: fused L2-normalize + fp16 hi limb; B: fp16 hi limb
    convert_a<<<BATCH, 256>>>((const float4*)pP, pAh);
    convert_b<<<(NCONCEPT * FDIM / 4) / 256, 256>>>((const float4*)prototypes, pBh);

    // 4) similarities via single-term fp16 mma.sync (f32 accum), 128x256 tiles
    sim_mma<<<dim3(BATCH / 128, NCONCEPT / 256), 512, SMEM_SIM>>>(pAh, pBh, pS);

    // 5) per-row softmax(S/T) + argmax (smem-staged, single S read)
    softmax_row<<<BATCH, 512, SMEM_SOFT>>>(pS, act, bidx);
}

// round 9
// speedup vs baseline: 4.7362x; 1.0111x over previous
#include <cuda_runtime.h>
#include <cuda_fp16.h>
#include <math.h>
#include <stdint.h>

// Problem constants
#define BATCH     1024
#define FDIM      1024
#define NCONCEPT  32768
#define INV_T     10.0f   // 1 / 0.1

#define TILE_B    16384          // one 128x64-fp16 swizzled tile (128 rows * 128 B)
#define KCHUNKS   16             // 1024 / 64
#define LO_SCALE  2048.0f        // 2^11

// sim pipeline: A (1 tile) + B (2 tiles) per stage = 48 KB, 4 stages (async)
#define STAGE_S   (3 * TILE_B)
#define NSTAGES_S 4
#define SMEM_SIM  (1024 + NSTAGES_S * STAGE_S)
// proj pipeline: Fhi, Flo, Whi, Wlo per stage = 64 KB, 3 stages
#define STAGE_P   (4 * TILE_B)
#define NSTAGES_P 3
#define SMEM_PROJ (1024 + NSTAGES_P * STAGE_P)
// softmax: full row staged in smem
#define SMEM_SOFT (NCONCEPT * 4)

// ---------------- scratch (device globals; no allocation allowed) ----------
__device__ float g_P[BATCH * FDIM];
__device__ float g_S[(size_t)BATCH * NCONCEPT];          // similarities (134 MB)
__device__ __align__(256) char g_Fh[(size_t)BATCH * FDIM * 2];
__device__ __align__(256) char g_Fl[(size_t)BATCH * FDIM * 2];
__device__ __align__(256) char g_Wh[(size_t)FDIM * FDIM * 2];
__device__ __align__(256) char g_Wl[(size_t)FDIM * FDIM * 2];
__device__ __align__(256) char g_Ah[(size_t)BATCH * FDIM * 2];
__device__ __align__(256) char g_Bh[(size_t)NCONCEPT * FDIM * 2];

// ---------------------------------------------------------------------------
// PTX helpers (baseline ISA only)
// ---------------------------------------------------------------------------
__device__ __forceinline__ uint32_t sm_u32(const void* p) {
    uint32_t a;
    asm("{ .reg .u64 t; cvta.to.shared.u64 t, %1; cvt.u32.u64 %0, t; }"
        : "=r"(a) : "l"(p));
    return a;
}

__device__ __forceinline__ void mbar_wait(uint32_t addr, int phase) {
    asm volatile(
        "{\n\t.reg .pred P;\n\t"
        "WL_%=:\n\t"
        "mbarrier.try_wait.parity.acquire.cta.shared::cta.b64 P, [%0], %1, 0x989680;\n\t"
        "@P bra.uni WD_%=;\n\t"
        "bra.uni WL_%=;\n\t"
        "WD_%=:\n\t}"
        :: "r"(addr), "r"((uint32_t)phase) : "memory");
}

#define MBAR_ARRIVE(addr) \
    asm volatile("mbarrier.arrive.shared.b64 _, [%0];" :: "r"(addr) : "memory")

#define LDSM4(R, addr) \
    asm volatile("ldmatrix.sync.aligned.m8n8.x4.shared.b16 {%0,%1,%2,%3}, [%4];" \
        : "=r"((R)[0]), "=r"((R)[1]), "=r"((R)[2]), "=r"((R)[3]) : "r"(addr))

#define MMA_F16_F32(C, A, b0_, b1_) \
    asm volatile("mma.sync.aligned.m16n8k16.row.col.f32.f16.f16.f32 " \
        "{%0,%1,%2,%3}, {%4,%5,%6,%7}, {%8,%9}, {%0,%1,%2,%3};" \
        : "+f"((C)[0]), "+f"((C)[1]), "+f"((C)[2]), "+f"((C)[3]) \
        : "r"((A)[0]), "r"((A)[1]), "r"((A)[2]), "r"((A)[3]), "r"(b0_), "r"(b1_))

#define MMA_F16_F16(C, A, b0_, b1_) \
    asm volatile("mma.sync.aligned.m16n8k16.row.col.f16.f16.f16.f16 " \
        "{%0,%1}, {%2,%3,%4,%5}, {%6,%7}, {%0,%1};" \
        : "+r"((C)[0]), "+r"((C)[1]) \
        : "r"((A)[0]), "r"((A)[1]), "r"((A)[2]), "r"((A)[3]), "r"(b0_), "r"(b1_))

#define BULK_LOAD(dst, src, bar) \
    asm volatile("cp.async.bulk.shared::cluster.global.mbarrier::complete_tx::bytes " \
        "[%0], [%1], %2, [%3];" \
        :: "r"(dst), "l"(src), "r"((uint32_t)TILE_B), "r"(bar) : "memory")

// ---------------------------------------------------------------------------
// fp32 -> fp16 two-limb split into pre-swizzled 128x64 tiles (no norm).
// ---------------------------------------------------------------------------
__global__ void __launch_bounds__(256)
convert_split2(const float4* __restrict__ src, char* __restrict__ hi, char* __restrict__ lo)
{
    const size_t i4 = (size_t)blockIdx.x * 256 + threadIdx.x;
    const int row = (int)(i4 >> 8);
    const int k   = ((int)i4 & 255) * 4;
    const float4 v = src[i4];
    const float x[4] = {v.x, v.y, v.z, v.w};

    unsigned short h[4], l[4];
#pragma unroll
    for (int j = 0; j < 4; ++j) {
        const __half hb = __float2half_rn(x[j]);
        const float r = (x[j] - __half2float(hb)) * LO_SCALE;
        h[j] = __half_as_ushort(hb);
        l[j] = __half_as_ushort(__float2half_rn(r));
    }

    const int tile = (row >> 7) * KCHUNKS + (k >> 6);
    uint32_t off = (uint32_t)((row & 127) * 128 + (k & 63) * 2);
    off ^= (off >> 3) & 0x70;

    uint2 ph, pl;
    ph.x = (uint32_t)h[0] | ((uint32_t)h[1] << 16);
    ph.y = (uint32_t)h[2] | ((uint32_t)h[3] << 16);
    pl.x = (uint32_t)l[0] | ((uint32_t)l[1] << 16);
    pl.y = (uint32_t)l[2] | ((uint32_t)l[3] << 16);
    *(uint2*)(hi + (size_t)tile * TILE_B + off) = ph;
    *(uint2*)(lo + (size_t)tile * TILE_B + off) = pl;
}

// ---------------------------------------------------------------------------
// A-side: fused L2-normalize + fp16 hi limb only. One CTA per row.
// ---------------------------------------------------------------------------
__global__ void __launch_bounds__(256)
convert_a(const float4* __restrict__ src, char* __restrict__ hi)
{
    const int row = blockIdx.x;
    const int tid = threadIdx.x;
    const float4 v = src[(size_t)row * 256 + tid];
    const float x[4] = {v.x, v.y, v.z, v.w};

    __shared__ float red[256];
    red[tid] = x[0]*x[0] + x[1]*x[1] + x[2]*x[2] + x[3]*x[3];
    __syncthreads();
#pragma unroll
    for (int off = 128; off > 0; off >>= 1) {
        if (tid < off) red[tid] += red[tid + off];
        __syncthreads();
    }
    const float inv = 1.0f / fmaxf(sqrtf(red[0]), 1e-12f);

    unsigned short h[4];
#pragma unroll
    for (int j = 0; j < 4; ++j)
        h[j] = __half_as_ushort(__float2half_rn(x[j] * inv));

    const int k = tid * 4;
    const int tile = (row >> 7) * KCHUNKS + (k >> 6);
    uint32_t off = (uint32_t)((row & 127) * 128 + (k & 63) * 2);
    off ^= (off >> 3) & 0x70;

    uint2 ph;
    ph.x = (uint32_t)h[0] | ((uint32_t)h[1] << 16);
    ph.y = (uint32_t)h[2] | ((uint32_t)h[3] << 16);
    *(uint2*)(hi + (size_t)tile * TILE_B + off) = ph;
}

// ---------------------------------------------------------------------------
// B-side: fp16 hi limb only, pre-swizzled tiles.
// ---------------------------------------------------------------------------
__global__ void __launch_bounds__(256)
convert_b(const float4* __restrict__ src, char* __restrict__ hi)
{
    const size_t i4 = (size_t)blockIdx.x * 256 + threadIdx.x;
    const int row = (int)(i4 >> 8);
    const int k   = ((int)i4 & 255) * 4;
    const float4 v = src[i4];
    const float x[4] = {v.x, v.y, v.z, v.w};

    unsigned short h[4];
#pragma unroll
    for (int j = 0; j < 4; ++j)
        h[j] = __half_as_ushort(__float2half_rn(x[j]));

    const int tile = (row >> 7) * KCHUNKS + (k >> 6);
    uint32_t off = (uint32_t)((row & 127) * 128 + (k & 63) * 2);
    off ^= (off >> 3) & 0x70;

    uint2 ph;
    ph.x = (uint32_t)h[0] | ((uint32_t)h[1] << 16);
    ph.y = (uint32_t)h[2] | ((uint32_t)h[3] << 16);
    *(uint2*)(hi + (size_t)tile * TILE_B + off) = ph;
}

// ---------------------------------------------------------------------------
// Projection GEMM, fp16 3-term limbs (~fp32). CTA 128x128, 16 warps.
// ---------------------------------------------------------------------------
__global__ void __launch_bounds__(512, 1)
proj_mma(const char* __restrict__ Fh, const char* __restrict__ Fl,
         const char* __restrict__ Wh, const char* __restrict__ Wl,
         const float* __restrict__ bias, float* __restrict__ P)
{
    extern __shared__ char smem_raw[];
    const uint32_t sbase = sm_u32(smem_raw);
    const uint32_t mbar0 = sbase;
    const uint32_t data0 = (sbase + 32u + 1023u) & ~1023u;

    const int tid = threadIdx.x;
    const int w = tid >> 5, l = tid & 31;
    const int wm = w & 3;
    const int wn = w >> 2;
    const int mb = blockIdx.x;
    const int nb = blockIdx.y;

    if (tid == 0) {
#pragma unroll
        for (int s = 0; s < NSTAGES_P; ++s)
            asm volatile("mbarrier.init.shared.b64 [%0], 1;" :: "r"(mbar0 + s * 8) : "memory");
    }
    __syncthreads();

    const int rowA  = wm * 32 + (l & 15);
    const uint32_t hA = (uint32_t)(l >> 4) << 4;
    const int rowB0 = wn * 32 + (l & 7) + ((l & 16) >> 1);
    const uint32_t hB = (uint32_t)(l & 8) << 1;
    const uint32_t swz = (uint32_t)(l & 7) << 4;

    float    acc[2][4][4];
    uint32_t accC[2][4][2];
#pragma unroll
    for (int i = 0; i < 2; ++i)
#pragma unroll
        for (int j = 0; j < 4; ++j) {
#pragma unroll
            for (int q = 0; q < 4; ++q) acc[i][j][q] = 0.f;
            accC[i][j][0] = 0u; accC[i][j][1] = 0u;
        }

    auto issue = [&](int kc, int s) {
        const uint32_t d = data0 + s * STAGE_P;
        const uint32_t bar = mbar0 + s * 8;
        const size_t aoff = ((size_t)mb * KCHUNKS + kc) * TILE_B;
        const size_t boff = ((size_t)nb * KCHUNKS + kc) * TILE_B;
        asm volatile("mbarrier.arrive.expect_tx.shared.b64 _, [%0], %1;"
                     :: "r"(bar), "r"((uint32_t)STAGE_P) : "memory");
        BULK_LOAD(d,              Fh + aoff, bar);
        BULK_LOAD(d + 1 * TILE_B, Fl + aoff, bar);
        BULK_LOAD(d + 2 * TILE_B, Wh + boff, bar);
        BULK_LOAD(d + 3 * TILE_B, Wl + boff, bar);
    };

    if (tid == 0) { issue(0, 0); issue(1, 1); }

    int ph[NSTAGES_P] = {0, 0, 0};

    for (int kc = 0; kc < KCHUNKS; ++kc) {
        const int s = kc % NSTAGES_P;
        mbar_wait(mbar0 + s * 8, ph[s]);
        ph[s] ^= 1;
        __syncthreads();
        if (tid == 0 && kc + 2 < KCHUNKS) issue(kc + 2, (kc + 2) % NSTAGES_P);

        const uint32_t aHb = data0 + s * STAGE_P;
        const uint32_t aLb = aHb + 1 * TILE_B;
        const uint32_t bHb = aHb + 2 * TILE_B;
        const uint32_t bLb = aHb + 3 * TILE_B;

#pragma unroll
        for (int ks = 0; ks < 4; ++ks) {
            uint32_t ah[2][4], al[2][4];
#pragma unroll
            for (int mi = 0; mi < 2; ++mi) {
                const uint32_t pa =
                    ((uint32_t)((rowA + mi * 16) * 128) + (uint32_t)(ks * 32) + hA) ^ swz;
                LDSM4(ah[mi], aHb + pa);
                LDSM4(al[mi], aLb + pa);
            }
#pragma unroll
            for (int nk = 0; nk < 2; ++nk) {
                const uint32_t pb =
                    ((uint32_t)((rowB0 + nk * 16) * 128) + (uint32_t)(ks * 32) + hB) ^ swz;
                uint32_t bh[4], bl[4];
                LDSM4(bh, bHb + pb);
                LDSM4(bl, bLb + pb);
#pragma unroll
                for (int mi = 0; mi < 2; ++mi) {
                    MMA_F16_F32(acc[mi][nk * 2 + 0], ah[mi], bh[0], bh[1]);
                    MMA_F16_F32(acc[mi][nk * 2 + 1], ah[mi], bh[2], bh[3]);
                    MMA_F16_F16(accC[mi][nk * 2 + 0], ah[mi], bl[0], bl[1]);
                    MMA_F16_F16(accC[mi][nk * 2 + 1], ah[mi], bl[2], bl[3]);
                    MMA_F16_F16(accC[mi][nk * 2 + 0], al[mi], bh[0], bh[1]);
                    MMA_F16_F16(accC[mi][nk * 2 + 1], al[mi], bh[2], bh[3]);
                }
            }
        }
    }

    const float cs = 1.0f / LO_SCALE;
    const int gm0 = mb * 128 + wm * 32 + (l >> 2);
    const int gn0 = nb * 128 + wn * 32 + (l & 3) * 2;
#pragma unroll
    for (int mi = 0; mi < 2; ++mi) {
#pragma unroll
        for (int nk = 0; nk < 2; ++nk) {
#pragma unroll
            for (int hf = 0; hf < 2; ++hf) {
                const int n = gn0 + nk * 16 + hf * 8;
                const float b0 = bias[n], b1 = bias[n + 1];
                const float* a = acc[mi][nk * 2 + hf];
                const uint32_t* c = accC[mi][nk * 2 + hf];
                const __half2 c0 = *(const __half2*)&c[0];
                const __half2 c1 = *(const __half2*)&c[1];
                float* p = P + (size_t)(gm0 + mi * 16) * FDIM + n;
                float2 v0, v1;
                v0.x = a[0] + __half2float(__low2half(c0))  * cs + b0;
                v0.y = a[1] + __half2float(__high2half(c0)) * cs + b1;
                v1.x = a[2] + __half2float(__low2half(c1))  * cs + b0;
                v1.y = a[3] + __half2float(__high2half(c1)) * cs + b1;
                *(float2*)p = v0;
                *(float2*)(p + (size_t)8 * FDIM) = v1;
            }
        }
    }
}

// ---------------------------------------------------------------------------
// Similarity GEMM, single-term fp16 (f32 accum). CTA tile 128x256, 16 warps.
// ASYNC pipeline: per-stage full (tx) + consumed (count 512) mbarriers; no
// __syncthreads in the mainloop — warps drift, producer refills on cons.
// 4 stages x 48 KB.
// ---------------------------------------------------------------------------
__global__ void __launch_bounds__(512, 1)
sim_mma(const char* __restrict__ Ah, const char* __restrict__ Bh,
        float* __restrict__ S)
{
    extern __shared__ char smem_raw[];
    const uint32_t sbase = sm_u32(smem_raw);
    const uint32_t full0 = sbase;            // 4 x 8B
    const uint32_t cons0 = sbase + 32;       // 4 x 8B
    const uint32_t data0 = (sbase + 64u + 1023u) & ~1023u;

    const int tid = threadIdx.x;
    const int w = tid >> 5, l = tid & 31;
    const int wm = w & 3;
    const int wn = w >> 2;
    const int mb = blockIdx.x;    // 0..7
    const int nb = blockIdx.y;    // 0..127

    if (tid == 0) {
#pragma unroll
        for (int s = 0; s < NSTAGES_S; ++s) {
            asm volatile("mbarrier.init.shared.b64 [%0], 1;"   :: "r"(full0 + s * 8) : "memory");
            asm volatile("mbarrier.init.shared.b64 [%0], 512;" :: "r"(cons0 + s * 8) : "memory");
        }
    }
    __syncthreads();

    const int rowA  = wm * 32 + (l & 15);
    const uint32_t hA = (uint32_t)(l >> 4) << 4;
    const int rowB0 = (wn & 1) * 64 + (l & 7) + ((l & 16) >> 1);
    const uint32_t hB = (uint32_t)(l & 8) << 1;
    const uint32_t swz = (uint32_t)(l & 7) << 4;
    const uint32_t bsel = (uint32_t)(wn >> 1) * TILE_B;

    float acc[2][8][4];
#pragma unroll
    for (int i = 0; i < 2; ++i)
#pragma unroll
        for (int j = 0; j < 8; ++j)
#pragma unroll
            for (int q = 0; q < 4; ++q) acc[i][j][q] = 0.f;

    auto issue = [&](int kc, int s) {
        const uint32_t d = data0 + s * STAGE_S;
        const uint32_t bar = full0 + s * 8;
        const size_t aoff  = ((size_t)mb * KCHUNKS + kc) * TILE_B;
        const size_t boff0 = ((size_t)(nb * 2 + 0) * KCHUNKS + kc) * TILE_B;
        const size_t boff1 = ((size_t)(nb * 2 + 1) * KCHUNKS + kc) * TILE_B;
        asm volatile("mbarrier.arrive.expect_tx.shared.b64 _, [%0], %1;"
                     :: "r"(bar), "r"((uint32_t)STAGE_S) : "memory");
        BULK_LOAD(d,              Ah + aoff,  bar);
        BULK_LOAD(d + 1 * TILE_B, Bh + boff0, bar);
        BULK_LOAD(d + 2 * TILE_B, Bh + boff1, bar);
    };

    if (tid == 0) { issue(0, 0); issue(1, 1); issue(2, 2); }

    int phf[NSTAGES_S] = {0, 0, 0, 0};
    int phc[NSTAGES_S] = {0, 0, 0, 0};   // used by tid 0 only

    for (int kc = 0; kc < KCHUNKS; ++kc) {
        const int s = kc & 3;
        mbar_wait(full0 + s * 8, phf[s]);
        phf[s] ^= 1;

        const uint32_t aHb = data0 + s * STAGE_S;
        const uint32_t bHb = aHb + TILE_B + bsel;

#pragma unroll
        for (int ks = 0; ks < 4; ++ks) {
            uint32_t ah[2][4];
#pragma unroll
            for (int mi = 0; mi < 2; ++mi) {
                const uint32_t pa =
                    ((uint32_t)((rowA + mi * 16) * 128) + (uint32_t)(ks * 32) + hA) ^ swz;
                LDSM4(ah[mi], aHb + pa);
            }
#pragma unroll
            for (int nk = 0; nk < 4; ++nk) {
                const uint32_t pb =
                    ((uint32_t)((rowB0 + nk * 16) * 128) + (uint32_t)(ks * 32) + hB) ^ swz;
                uint32_t bh[4];
                LDSM4(bh, bHb + pb);
#pragma unroll
                for (int mi = 0; mi < 2; ++mi) {
                    MMA_F16_F32(acc[mi][nk * 2 + 0], ah[mi], bh[0], bh[1]);
                    MMA_F16_F32(acc[mi][nk * 2 + 1], ah[mi], bh[2], bh[3]);
                }
            }
        }

        MBAR_ARRIVE(cons0 + s * 8);

        if (tid == 0 && kc + 3 < KCHUNKS) {
            const int s2 = (kc + 3) & 3;
            if (kc >= 1) {                 // stage s2 was used by chunk kc-1
                mbar_wait(cons0 + s2 * 8, phc[s2]);
                phc[s2] ^= 1;
            }
            issue(kc + 3, s2);
        }
    }

    const int gm0 = mb * 128 + wm * 32 + (l >> 2);
    const int gn0 = nb * 256 + wn * 64 + (l & 3) * 2;
#pragma unroll
    for (int mi = 0; mi < 2; ++mi) {
#pragma unroll
        for (int nk = 0; nk < 4; ++nk) {
#pragma unroll
            for (int hf = 0; hf < 2; ++hf) {
                const float* a = acc[mi][nk * 2 + hf];
                float* p = S + (size_t)(gm0 + mi * 16) * NCONCEPT + gn0 + nk * 16 + hf * 8;
                float2 v0, v1;
                v0.x = a[0]; v0.y = a[1];
                v1.x = a[2]; v1.y = a[3];
                *(float2*)p = v0;
                *(float2*)(p + (size_t)8 * NCONCEPT) = v1;
            }
        }
    }
}

// ---------------------------------------------------------------------------
// Per-row softmax(sim * INV_T) + argmax, row staged in SMEM (single S read).
// One CTA (512 threads) per row; 128 KB dynamic smem.
// ---------------------------------------------------------------------------
__global__ void __launch_bounds__(512)
softmax_row(const float* __restrict__ S,
            float* __restrict__ act,
            float* __restrict__ bidx)
{
    extern __shared__ float srow[];
    const int row = blockIdx.x;
    const int tid = threadIdx.x;
    const float4* s4 = (const float4*)(S + (size_t)row * NCONCEPT);
    float4* r4 = (float4*)srow;

    float m = -INFINITY;
    float Z = 0.f;
    int   bi = 0;

    for (int j = tid; j < NCONCEPT / 4; j += 512) {
        const float4 v = s4[j];
        r4[j] = v;
        const float x[4] = {v.x, v.y, v.z, v.w};
#pragma unroll
        for (int q = 0; q < 4; ++q) {
            if (x[q] > m) {
                Z = Z * __expf((m - x[q]) * INV_T) + 1.0f;
                m = x[q];
                bi = j * 4 + q;
            } else {
                Z += __expf((x[q] - m) * INV_T);
            }
        }
    }

    __shared__ float sm[512];
    __shared__ float sz[512];
    __shared__ int   si[512];
    sm[tid] = m; sz[tid] = Z; si[tid] = bi;
    __syncthreads();

#pragma unroll
    for (int off = 256; off > 0; off >>= 1) {
        if (tid < off) {
            const float m1 = sm[tid],       z1 = sz[tid];
            const float m2 = sm[tid + off], z2 = sz[tid + off];
            const int   i1 = si[tid],       i2 = si[tid + off];
            if (m2 > m1 || (m2 == m1 && i2 < i1)) {
                sm[tid] = m2;
                sz[tid] = z2 + z1 * __expf((m1 - m2) * INV_T);
                si[tid] = i2;
            } else {
                sz[tid] = z1 + z2 * __expf((m2 - m1) * INV_T);
            }
        }
        __syncthreads();
    }

    const float M    = sm[0];
    const float invZ = 1.0f / sz[0];
    float4* a4 = (float4*)(act + (size_t)row * NCONCEPT);
    for (int j = tid; j < NCONCEPT / 4; j += 512) {
        const float4 v = r4[j];
        float4 o;
        o.x = __expf((v.x - M) * INV_T) * invZ;
        o.y = __expf((v.y - M) * INV_T) * invZ;
        o.z = __expf((v.z - M) * INV_T) * invZ;
        o.w = __expf((v.w - M) * INV_T) * invZ;
        a4[j] = o;
    }

    if (tid == 0) bidx[row] = (float)si[0];
}

// ---------------------------------------------------------------------------
extern "C" void kernel_launch(void* const* d_in, const int* in_sizes, int n_in,
                              void* d_out, int out_size)
{
    const float* features   = (const float*)d_in[0];  // [1024, 1024]
    const float* W          = (const float*)d_in[1];  // [1024, 1024]
    const float* b          = (const float*)d_in[2];  // [1024]
    const float* prototypes = (const float*)d_in[3];  // [32768, 1024]

    float* out  = (float*)d_out;
    float* act  = out;                                   // [1024, 32768]
    float* bidx = out + (size_t)BATCH * NCONCEPT;        // [1024] as float

    float *pP = nullptr, *pS = nullptr;
    char *pFh = nullptr, *pFl = nullptr, *pWh = nullptr, *pWl = nullptr;
    char *pAh = nullptr, *pBh = nullptr;
    cudaGetSymbolAddress((void**)&pP,  g_P);
    cudaGetSymbolAddress((void**)&pS,  g_S);
    cudaGetSymbolAddress((void**)&pFh, g_Fh);
    cudaGetSymbolAddress((void**)&pFl, g_Fl);
    cudaGetSymbolAddress((void**)&pWh, g_Wh);
    cudaGetSymbolAddress((void**)&pWl, g_Wl);
    cudaGetSymbolAddress((void**)&pAh, g_Ah);
    cudaGetSymbolAddress((void**)&pBh, g_Bh);

    cudaFuncSetAttribute(proj_mma, cudaFuncAttributeMaxDynamicSharedMemorySize, SMEM_PROJ);
    cudaFuncSetAttribute(sim_mma,  cudaFuncAttributeMaxDynamicSharedMemorySize, SMEM_SIM);
    cudaFuncSetAttribute(softmax_row, cudaFuncAttributeMaxDynamicSharedMemorySize, SMEM_SOFT);

    // 1) split features and W into fp16 limbs (pre-swizzled tiles)
    convert_split2<<<(BATCH * FDIM / 4) / 256, 256>>>((const float4*)features, pFh, pFl);
    convert_split2<<<(FDIM * FDIM / 4) / 256, 256>>>((const float4*)W, pWh, pWl);

    // 2) projection via fp16 3-term mma: P = F @ W^T + b
    proj_mma<<<dim3(BATCH / 128, FDIM / 128), 512, SMEM_PROJ>>>(
        pFh, pFl, pWh, pWl, b, pP);

    // 3) A: fused L2-normalize + fp16 hi limb; B: fp16 hi limb
    convert_a<<<BATCH, 256>>>((const float4*)pP, pAh);
    convert_b<<<(NCONCEPT * FDIM / 4) / 256, 256>>>((const float4*)prototypes, pBh);

    // 4) similarities via single-term fp16 mma.sync, async-barrier pipeline
    sim_mma<<<dim3(BATCH / 128, NCONCEPT / 256), 512, SMEM_SIM>>>(pAh, pBh, pS);

    // 5) per-row softmax(S/T) + argmax (smem-staged, single S read)
    softmax_row<<<BATCH, 512, SMEM_SOFT>>>(pS, act, bidx);
}